// round 10
// baseline (speedup 1.0000x reference)
#include <cuda_runtime.h>
#include <cuda_bf16.h>
#include <math.h>
#include <stdint.h>

// Problem constants
#define B_   2
#define S_   2048
#define E_   2048
#define H_   16
#define KVH_ 4
#define D_   128
#define M_   (B_ * S_)        // 4096 rows
#define KVN_ (2 * KVH_ * D_)  // 1024

// ---------------- scratch (device globals; no allocs allowed) ----------------
__device__ float g_qproj[(size_t)M_ * E_];
__device__ float g_kvproj[(size_t)M_ * KVN_];

__device__ unsigned short g_xhi[(size_t)M_ * E_];
__device__ unsigned short g_xlo[(size_t)M_ * E_];
__device__ unsigned short g_wqhi[(size_t)E_ * E_];
__device__ unsigned short g_wqlo[(size_t)E_ * E_];
__device__ unsigned short g_wkvhi[(size_t)KVN_ * E_];
__device__ unsigned short g_wkvlo[(size_t)KVN_ * E_];
__device__ unsigned short g_wohi[(size_t)E_ * E_];
__device__ unsigned short g_wolo[(size_t)E_ * E_];
__device__ unsigned short g_aohi[(size_t)M_ * E_];
__device__ unsigned short g_aolo[(size_t)M_ * E_];
// flash operands
__device__ signed char g_q1[(size_t)M_ * E_];      // int8 limb1 of rope'd Q
__device__ signed char g_q0[(size_t)M_ * E_];      // int8 limb0
__device__ signed char g_k1[(size_t)M_ * (KVH_ * D_)];
__device__ signed char g_k0[(size_t)M_ * (KVH_ * D_)];
__device__ float g_qs2[(size_t)M_ * H_];           // per (m,h) scale (incl log2e/sqrt(D)/127)
__device__ float g_ksc[(size_t)B_ * KVH_ * S_];    // per (b,kvh,s) scale (/127)
__device__ unsigned short g_vthi[(size_t)B_ * KVH_ * D_ * S_];
__device__ unsigned short g_vtlo[(size_t)B_ * KVH_ * D_ * S_];

// ============================ PTX helpers ====================================
__device__ __forceinline__ uint32_t smem_u32(const void* p) {
    uint32_t a;
    asm("{ .reg .u64 t; cvta.to.shared.u64 t, %1; cvt.u32.u64 %0, t; }"
        : "=r"(a) : "l"(p));
    return a;
}
__device__ __forceinline__ void cp_async16(uint32_t dst, const void* src) {
    asm volatile("cp.async.cg.shared.global [%0], [%1], 16;"
                 :: "r"(dst), "l"(src) : "memory");
}
__device__ __forceinline__ void cp_commit() {
    asm volatile("cp.async.commit_group;" ::: "memory");
}
template <int N>
__device__ __forceinline__ void cp_wait() {
    asm volatile("cp.async.wait_group %0;" :: "n"(N) : "memory");
}
__device__ __forceinline__ uint32_t lds32(uint32_t addr) {
    uint32_t v;
    asm volatile("ld.shared.b32 %0, [%1];" : "=r"(v) : "r"(addr));
    return v;
}
__device__ __forceinline__ void ldmx4(uint32_t& r0, uint32_t& r1, uint32_t& r2,
                                      uint32_t& r3, uint32_t addr) {
    asm volatile("ldmatrix.sync.aligned.m8n8.x4.shared.b16 {%0,%1,%2,%3}, [%4];"
                 : "=r"(r0), "=r"(r1), "=r"(r2), "=r"(r3) : "r"(addr));
}
__device__ __forceinline__ void mma_bf16(float& d0, float& d1, float& d2, float& d3,
                                         uint32_t a0, uint32_t a1, uint32_t a2,
                                         uint32_t a3, uint32_t b0, uint32_t b1) {
    asm volatile(
        "mma.sync.aligned.m16n8k16.row.col.f32.bf16.bf16.f32 "
        "{%0,%1,%2,%3}, {%4,%5,%6,%7}, {%8,%9}, {%0,%1,%2,%3};"
        : "+f"(d0), "+f"(d1), "+f"(d2), "+f"(d3)
        : "r"(a0), "r"(a1), "r"(a2), "r"(a3), "r"(b0), "r"(b1));
}
__device__ __forceinline__ void imma8(int* d, const uint32_t* a, uint32_t b0, uint32_t b1) {
    asm volatile(
        "mma.sync.aligned.m16n8k32.row.col.s32.s8.s8.s32 "
        "{%0,%1,%2,%3}, {%4,%5,%6,%7}, {%8,%9}, {%0,%1,%2,%3};"
        : "+r"(d[0]), "+r"(d[1]), "+r"(d[2]), "+r"(d[3])
        : "r"(a[0]), "r"(a[1]), "r"(a[2]), "r"(a[3]), "r"(b0), "r"(b1));
}
__device__ __forceinline__ float ex2f(float x) {
    float y;
    asm("ex2.approx.ftz.f32 %0, %1;" : "=f"(y) : "f"(x));
    return y;
}
__device__ __forceinline__ uint32_t packbf(float a, float b) {
    __nv_bfloat162 t = __floats2bfloat162_rn(a, b);
    return *(uint32_t*)&t;
}

// ====================== fp32 -> bf16 hi/lo split =============================
__device__ __forceinline__ void split1(float x, unsigned short& h, unsigned short& l) {
    __nv_bfloat16 bh = __float2bfloat16_rn(x);
    float r = x - __bfloat162float(bh);
    __nv_bfloat16 bl = __float2bfloat16_rn(r);
    h = __bfloat16_as_ushort(bh);
    l = __bfloat16_as_ushort(bl);
}
__global__ void __launch_bounds__(256) split_bf16(const float* __restrict__ in,
                                                  unsigned short* __restrict__ hi,
                                                  unsigned short* __restrict__ lo,
                                                  int n4) {
    int i = blockIdx.x * blockDim.x + threadIdx.x;
    if (i >= n4) return;
    float4 v = ((const float4*)in)[i];
    ushort4 h, l;
    split1(v.x, h.x, l.x);
    split1(v.y, h.y, l.y);
    split1(v.z, h.z, l.z);
    split1(v.w, h.w, l.w);
    ((ushort4*)hi)[i] = h;
    ((ushort4*)lo)[i] = l;
}

// ============ RoPE fused with int8 2-limb quantization (Q) ===================
// One warp per (m, h). Output: q1/q0 [M,E] s8 (head-major), qs2 [M,H] scale.
__global__ void __launch_bounds__(256)
rope_q_quant(const float* __restrict__ proj, signed char* __restrict__ q1,
             signed char* __restrict__ q0, float* __restrict__ qs2) {
    const int wi = blockIdx.x * 8 + (threadIdx.x >> 5);
    const int lane = threadIdx.x & 31;
    const int m = wi >> 4;
    const int h = wi & 15;
    const float* p = proj + (size_t)m * E_ + h * 128;
    const int s = m & (S_ - 1);
    float f0 = (float)s * powf(10000.0f, -(float)lane * (1.0f / 64.0f));
    float f1 = (float)s * powf(10000.0f, -(float)(lane + 32) * (1.0f / 64.0f));
    float sn0, cs0, sn1, cs1;
    sincosf(f0, &sn0, &cs0);
    sincosf(f1, &sn1, &cs1);
    float v0 = p[lane], v64 = p[lane + 64], v32 = p[lane + 32], v96 = p[lane + 96];
    float o0  = v0  * cs0 - v64 * sn0;
    float o64 = v64 * cs0 + v0  * sn0;
    float o32 = v32 * cs1 - v96 * sn1;
    float o96 = v96 * cs1 + v32 * sn1;
    float am = fmaxf(fmaxf(fabsf(o0), fabsf(o64)), fmaxf(fabsf(o32), fabsf(o96)));
#pragma unroll
    for (int off = 16; off; off >>= 1)
        am = fmaxf(am, __shfl_xor_sync(0xffffffffu, am, off));
    am = fmaxf(am, 1e-20f);
    const float inv = 127.0f / am;
    const size_t bi = (size_t)m * E_ + h * 128;
    auto qz = [&](float v, size_t idx) {
        float a = v * inv;
        int hh = __float2int_rn(a);
        int ll = __float2int_rn((a - (float)hh) * 128.0f);
        q1[idx] = (signed char)hh;
        q0[idx] = (signed char)ll;
    };
    qz(o0,  bi + lane);
    qz(o64, bi + lane + 64);
    qz(o32, bi + lane + 32);
    qz(o96, bi + lane + 96);
    if (lane == 0)
        qs2[(size_t)m * H_ + h] = am * (0.127518795f / 127.0f);  // log2e/sqrt(128)/127
}

// ============ RoPE fused with int8 2-limb quantization (K) ===================
// One warp per (m, kvh). k1/k0 [M, 512] s8; ksc [(b*KVH+kvh)*S + s].
__global__ void __launch_bounds__(256)
rope_k_quant(const float* __restrict__ proj, signed char* __restrict__ k1,
             signed char* __restrict__ k0, float* __restrict__ ksc) {
    const int wi = blockIdx.x * 8 + (threadIdx.x >> 5);
    const int lane = threadIdx.x & 31;
    const int m = wi >> 2;
    const int kvh = wi & 3;
    const float* p = proj + (size_t)m * KVN_ + kvh * 128;
    const int s = m & (S_ - 1);
    float f0 = (float)s * powf(10000.0f, -(float)lane * (1.0f / 64.0f));
    float f1 = (float)s * powf(10000.0f, -(float)(lane + 32) * (1.0f / 64.0f));
    float sn0, cs0, sn1, cs1;
    sincosf(f0, &sn0, &cs0);
    sincosf(f1, &sn1, &cs1);
    float v0 = p[lane], v64 = p[lane + 64], v32 = p[lane + 32], v96 = p[lane + 96];
    float o0  = v0  * cs0 - v64 * sn0;
    float o64 = v64 * cs0 + v0  * sn0;
    float o32 = v32 * cs1 - v96 * sn1;
    float o96 = v96 * cs1 + v32 * sn1;
    float am = fmaxf(fmaxf(fabsf(o0), fabsf(o64)), fmaxf(fabsf(o32), fabsf(o96)));
#pragma unroll
    for (int off = 16; off; off >>= 1)
        am = fmaxf(am, __shfl_xor_sync(0xffffffffu, am, off));
    am = fmaxf(am, 1e-20f);
    const float inv = 127.0f / am;
    const size_t bi = (size_t)m * 512 + kvh * 128;
    auto qz = [&](float v, size_t idx) {
        float a = v * inv;
        int hh = __float2int_rn(a);
        int ll = __float2int_rn((a - (float)hh) * 128.0f);
        k1[idx] = (signed char)hh;
        k0[idx] = (signed char)ll;
    };
    qz(o0,  bi + lane);
    qz(o64, bi + lane + 64);
    qz(o32, bi + lane + 32);
    qz(o96, bi + lane + 96);
    if (lane == 0) {
        const int b = m >> 11, ss = m & (S_ - 1);
        ksc[(size_t)(b * KVH_ + kvh) * S_ + ss] = am * (1.0f / 127.0f);
    }
}

// ============ V transpose + split: kvproj V-part -> VT[d, s] bf16 ============
__global__ void __launch_bounds__(256) vtrans_split(const float* __restrict__ kv,
                                                    unsigned short* __restrict__ vthi,
                                                    unsigned short* __restrict__ vtlo) {
    __shared__ float t[32][33];
    const int s0 = blockIdx.x * 32, d0 = blockIdx.y * 32;
    const int bk = blockIdx.z;
    const int b = bk >> 2, kvh = bk & 3;
    const int tx = threadIdx.x & 31, ty = threadIdx.x >> 5;
#pragma unroll
    for (int i = 0; i < 4; i++) {
        int s = s0 + ty + i * 8;
        t[ty + i * 8][tx] =
            kv[(size_t)(b * S_ + s) * KVN_ + KVH_ * D_ + kvh * 128 + d0 + tx];
    }
    __syncthreads();
#pragma unroll
    for (int i = 0; i < 4; i++) {
        int d = d0 + ty + i * 8;
        float v = t[tx][ty + i * 8];
        unsigned short hi, lo;
        split1(v, hi, lo);
        size_t o = ((size_t)bk * 128 + d) * S_ + s0 + tx;
        vthi[o] = hi;
        vtlo[o] = lo;
    }
}

// =============== HMMA GEMM: C = A@W^T (+bias), 3x bf16 split =================
#define GS_STRIDE 80
#define GS_BUF    (128 * GS_STRIDE)

__global__ void __launch_bounds__(256)
gemm_hmma_x3(const unsigned short* __restrict__ Ahi, const unsigned short* __restrict__ Alo,
             const unsigned short* __restrict__ Bhi, const unsigned short* __restrict__ Blo,
             const float* __restrict__ bias, float* __restrict__ C,
             int M, int N, int K) {
    __shared__ __align__(16) unsigned char smem[4 * GS_BUF];
    const uint32_t sb = smem_u32(smem);
    const int tid = threadIdx.x;
    const int wid = tid >> 5, lane = tid & 31;
    const int wm = wid & 3;
    const int wn = wid >> 2;
    const int m0 = blockIdx.y * 128, n0 = blockIdx.x * 128;

    const int NCH = 3 * (K >> 5);
    const int segC = K >> 5;

    float acc[2][8][4];
#pragma unroll
    for (int mt = 0; mt < 2; mt++)
#pragma unroll
        for (int nt = 0; nt < 8; nt++)
#pragma unroll
            for (int i = 0; i < 4; i++) acc[mt][nt][i] = 0.f;

    auto issue = [&](int c, int buf) {
        const int seg = c / segC;
        const int kk = (c % segC) << 5;
        const unsigned short* Ap = (seg == 2) ? Alo : Ahi;
        const unsigned short* Bp = (seg == 1) ? Blo : Bhi;
#pragma unroll
        for (int h = 0; h < 2; h++) {
            const int u = tid + h * 256;
            const int row = u >> 2;
            const int kb = (u & 3) << 3;
            cp_async16(sb + buf * GS_BUF + row * GS_STRIDE + (kb << 1),
                       Ap + (size_t)(m0 + row) * K + kk + kb);
            cp_async16(sb + 2 * GS_BUF + buf * GS_BUF + row * GS_STRIDE + (kb << 1),
                       Bp + (size_t)(n0 + row) * K + kk + kb);
        }
        cp_commit();
    };

    issue(0, 0);
    int buf = 0;
    for (int c = 0; c < NCH; c++) {
        if (c + 1 < NCH) { issue(c + 1, buf ^ 1); cp_wait<1>(); }
        else             { cp_wait<0>(); }
        __syncthreads();

        const uint32_t abase = sb + buf * GS_BUF;
        const uint32_t bbase = sb + 2 * GS_BUF + buf * GS_BUF;
#pragma unroll
        for (int ks = 0; ks < 2; ks++) {
            const int kbyte = ks * 32;
            uint32_t a[2][4];
#pragma unroll
            for (int mt = 0; mt < 2; mt++) {
                const int row = wm * 32 + mt * 16 + (lane & 15);
                ldmx4(a[mt][0], a[mt][1], a[mt][2], a[mt][3],
                      abase + row * GS_STRIDE + kbyte + ((lane >> 4) << 4));
            }
            uint32_t b[8][2];
#pragma unroll
            for (int np = 0; np < 4; np++) {
                const int row = wn * 64 + np * 16 + (((lane >> 4) & 1) << 3) + (lane & 7);
                uint32_t r0, r1, r2, r3;
                ldmx4(r0, r1, r2, r3,
                      bbase + row * GS_STRIDE + kbyte + (((lane >> 3) & 1) << 4));
                b[np * 2][0] = r0; b[np * 2][1] = r1;
                b[np * 2 + 1][0] = r2; b[np * 2 + 1][1] = r3;
            }
#pragma unroll
            for (int mt = 0; mt < 2; mt++)
#pragma unroll
                for (int nt = 0; nt < 8; nt++)
                    mma_bf16(acc[mt][nt][0], acc[mt][nt][1],
                             acc[mt][nt][2], acc[mt][nt][3],
                             a[mt][0], a[mt][1], a[mt][2], a[mt][3],
                             b[nt][0], b[nt][1]);
        }
        __syncthreads();
        buf ^= 1;
    }

    const int mrow = m0 + wm * 32 + (lane >> 2);
    const int ncol0 = n0 + wn * 64 + ((lane & 3) << 1);
#pragma unroll
    for (int mt = 0; mt < 2; mt++) {
#pragma unroll
        for (int nt = 0; nt < 8; nt++) {
            const int n = ncol0 + nt * 8;
            float b0 = bias ? bias[n] : 0.f;
            float b1 = bias ? bias[n + 1] : 0.f;
            float2 v0 = make_float2(acc[mt][nt][0] + b0, acc[mt][nt][1] + b1);
            float2 v1 = make_float2(acc[mt][nt][2] + b0, acc[mt][nt][3] + b1);
            *(float2*)&C[(size_t)(mrow + mt * 16) * N + n] = v0;
            *(float2*)&C[(size_t)(mrow + mt * 16 + 8) * N + n] = v1;
        }
    }
}

// ================= flash attention: int8 QK + bf16x3 PV ======================
// CTA: 128 q rows, 8 warps. KV tile BN=64, double-buffered stages.
#define F3_Q1   0
#define F3_Q0   18432
#define F3_ST0  36864
#define F3_STG  55296
#define F3_K1   0
#define F3_K0   9216
#define F3_VHI  18432
#define F3_VLO  36864
#define F3_SMEM (F3_ST0 + 2 * F3_STG)   // 147456 B

__global__ void __launch_bounds__(256)
flash_hmma(const signed char* __restrict__ q1g, const signed char* __restrict__ q0g,
           const signed char* __restrict__ k1g, const signed char* __restrict__ k0g,
           const unsigned short* __restrict__ vthi, const unsigned short* __restrict__ vtlo,
           const float* __restrict__ qs2g, const float* __restrict__ kscg,
           unsigned short* __restrict__ Ohi, unsigned short* __restrict__ Olo) {
    extern __shared__ __align__(16) unsigned char fsm2[];
    const uint32_t sb = smem_u32(fsm2);
    const int tid = threadIdx.x;
    const int w = tid >> 5, lane = tid & 31;
    const int bh = blockIdx.y;
    const int b = bh >> 4, h = bh & 15;
    const int kvh = h >> 2;
    const int q0r = blockIdx.x * 128;

    const signed char* q1p = q1g + (size_t)(b * S_ + q0r) * E_ + h * 128;
    const signed char* q0p = q0g + (size_t)(b * S_ + q0r) * E_ + h * 128;
    const signed char* k1p = k1g + (size_t)b * S_ * 512 + kvh * 128;
    const signed char* k0p = k0g + (size_t)b * S_ * 512 + kvh * 128;
    const unsigned short* vhp = vthi + ((size_t)(b * KVH_ + kvh) * 128) * S_;
    const unsigned short* vlp = vtlo + ((size_t)(b * KVH_ + kvh) * 128) * S_;
    const float* kscB = kscg + (size_t)(b * KVH_ + kvh) * S_;

    auto load_q128 = [&](uint32_t dst, const signed char* src) {
#pragma unroll
        for (int it = 0; it < 4; it++) {
            int u = tid + it * 256;          // 128 rows x 128B
            int row = u >> 3;
            int cb = (u & 7) << 4;
            cp_async16(sb + dst + row * 144 + cb, src + (size_t)row * E_ + cb);
        }
    };
    auto issue_stage = [&](int stg, int kv0) {
        const uint32_t base = F3_ST0 + stg * F3_STG;
#pragma unroll
        for (int it = 0; it < 2; it++) {
            int u = tid + it * 256;          // 64 rows x 128B
            int row = u >> 3;
            int cb = (u & 7) << 4;
            cp_async16(sb + base + F3_K1 + row * 144 + cb,
                       k1p + (size_t)(kv0 + row) * 512 + cb);
            cp_async16(sb + base + F3_K0 + row * 144 + cb,
                       k0p + (size_t)(kv0 + row) * 512 + cb);
        }
#pragma unroll
        for (int it = 0; it < 4; it++) {
            int u = tid + it * 256;          // 128 rows x 128B
            int row = u >> 3;
            int cb = (u & 7) << 4;
            cp_async16(sb + base + F3_VHI + row * 144 + cb,
                       (const char*)(vhp + kv0) + (size_t)row * S_ * 2 + cb);
            cp_async16(sb + base + F3_VLO + row * 144 + cb,
                       (const char*)(vlp + kv0) + (size_t)row * S_ * 2 + cb);
        }
        cp_commit();
    };

    load_q128(F3_Q1, q1p);
    load_q128(F3_Q0, q0p);
    issue_stage(0, 0);
    cp_wait<0>();
    __syncthreads();

    float oacc[16][4];
#pragma unroll
    for (int nt = 0; nt < 16; nt++)
#pragma unroll
        for (int i = 0; i < 4; i++) oacc[nt][i] = 0.f;
    float m0 = -1e30f, m1 = -1e30f, l0 = 0.f, l1 = 0.f;

    // int8 fragment addressing (m16n8k32 thread map)
    const int qr = w * 16 + (lane >> 2);
    const uint32_t aQ1 = sb + F3_Q1 + qr * 144 + (lane & 3) * 4;
    const uint32_t aQ0 = sb + F3_Q0 + qr * 144 + (lane & 3) * 4;
    const int bc = lane >> 2;
    const uint32_t bkb = (lane & 3) * 4;
    // bf16 V fragment addressing (as before)
    const int brow = (((lane >> 4) & 1) << 3) + (lane & 7);
    const uint32_t bvo = brow * 144 + (((lane >> 3) & 1) << 4);

    const float qs2a = qs2g[(size_t)(b * S_ + q0r + qr) * H_ + h];
    const float qs2b = qs2g[(size_t)(b * S_ + q0r + qr + 8) * H_ + h];

    int buf = 0;
    for (int kt = 0; kt < S_ / 64; kt++) {
        if (kt + 1 < S_ / 64) issue_stage(buf ^ 1, (kt + 1) * 64);
        const uint32_t sk = sb + F3_ST0 + buf * F3_STG;

        int acc1[8][4], accx[8][4];
#pragma unroll
        for (int g = 0; g < 8; g++)
#pragma unroll
            for (int i = 0; i < 4; i++) { acc1[g][i] = 0; accx[g][i] = 0; }

        // ---- S = Q K^T via int8 2-limb IMMA ----
#pragma unroll
        for (int ks = 0; ks < 4; ks++) {
            uint32_t a1r[4], a0r[4];
            uint32_t qa = aQ1 + ks * 32;
            a1r[0] = lds32(qa);        a1r[1] = lds32(qa + 1152);
            a1r[2] = lds32(qa + 16);   a1r[3] = lds32(qa + 1168);
            qa = aQ0 + ks * 32;
            a0r[0] = lds32(qa);        a0r[1] = lds32(qa + 1152);
            a0r[2] = lds32(qa + 16);   a0r[3] = lds32(qa + 1168);
#pragma unroll
            for (int g = 0; g < 8; g++) {
                const uint32_t ka = sk + F3_K1 + (g * 8 + bc) * 144 + bkb + ks * 32;
                uint32_t b1a = lds32(ka), b1b = lds32(ka + 16);
                uint32_t b0a = lds32(ka + 9216), b0b = lds32(ka + 9232);
                imma8(acc1[g], a1r, b1a, b1b);
                imma8(accx[g], a1r, b0a, b0b);
                imma8(accx[g], a0r, b1a, b1b);
            }
        }

        // ---- reconstruct logits (base-2 domain; scales folded) ----
        float sacc[8][4];
#pragma unroll
        for (int g = 0; g < 8; g++) {
            const float2 kv2 =
                *(const float2*)&kscB[kt * 64 + g * 8 + ((lane & 3) << 1)];
            sacc[g][0] = qs2a * kv2.x * ((float)acc1[g][0] + (float)accx[g][0] * 0.0078125f);
            sacc[g][1] = qs2a * kv2.y * ((float)acc1[g][1] + (float)accx[g][1] * 0.0078125f);
            sacc[g][2] = qs2b * kv2.x * ((float)acc1[g][2] + (float)accx[g][2] * 0.0078125f);
            sacc[g][3] = qs2b * kv2.y * ((float)acc1[g][3] + (float)accx[g][3] * 0.0078125f);
        }

        // ---- online softmax ----
        float mx0 = -1e30f, mx1 = -1e30f;
#pragma unroll
        for (int nt = 0; nt < 8; nt++) {
            mx0 = fmaxf(mx0, fmaxf(sacc[nt][0], sacc[nt][1]));
            mx1 = fmaxf(mx1, fmaxf(sacc[nt][2], sacc[nt][3]));
        }
        mx0 = fmaxf(mx0, __shfl_xor_sync(0xffffffffu, mx0, 1));
        mx0 = fmaxf(mx0, __shfl_xor_sync(0xffffffffu, mx0, 2));
        mx1 = fmaxf(mx1, __shfl_xor_sync(0xffffffffu, mx1, 1));
        mx1 = fmaxf(mx1, __shfl_xor_sync(0xffffffffu, mx1, 2));
        const float mn0 = fmaxf(m0, mx0), mn1 = fmaxf(m1, mx1);
        const float c0 = ex2f(m0 - mn0), c1 = ex2f(m1 - mn1);
        m0 = mn0; m1 = mn1;
        float sum0 = 0.f, sum1 = 0.f;
#pragma unroll
        for (int nt = 0; nt < 8; nt++) {
            sacc[nt][0] = ex2f(sacc[nt][0] - mn0);
            sacc[nt][1] = ex2f(sacc[nt][1] - mn0);
            sacc[nt][2] = ex2f(sacc[nt][2] - mn1);
            sacc[nt][3] = ex2f(sacc[nt][3] - mn1);
            sum0 += sacc[nt][0] + sacc[nt][1];
            sum1 += sacc[nt][2] + sacc[nt][3];
        }
#pragma unroll
        for (int nt = 0; nt < 16; nt++) {
            oacc[nt][0] *= c0; oacc[nt][1] *= c0;
            oacc[nt][2] *= c1; oacc[nt][3] *= c1;
        }
        sum0 += __shfl_xor_sync(0xffffffffu, sum0, 1);
        sum0 += __shfl_xor_sync(0xffffffffu, sum0, 2);
        sum1 += __shfl_xor_sync(0xffffffffu, sum1, 1);
        sum1 += __shfl_xor_sync(0xffffffffu, sum1, 2);
        l0 = l0 * c0 + sum0;
        l1 = l1 * c1 + sum1;

        // ---- O += P V (bf16 3-way split; P split in registers) ----
#pragma unroll
        for (int j = 0; j < 4; j++) {
            const float* p0 = sacc[2 * j];
            const float* p1 = sacc[2 * j + 1];
            uint32_t aph[4], apl[4];
            aph[0] = packbf(p0[0], p0[1]);
            aph[1] = packbf(p0[2], p0[3]);
            aph[2] = packbf(p1[0], p1[1]);
            aph[3] = packbf(p1[2], p1[3]);
#pragma unroll
            for (int q = 0; q < 4; q++) {
                const float* pp = (q < 2) ? p0 : p1;
                const int o = (q & 1) * 2;
                float2 f = __bfloat1622float2(*(__nv_bfloat162*)&aph[q]);
                apl[q] = packbf(pp[o] - f.x, pp[o + 1] - f.y);
            }
#pragma unroll
            for (int np = 0; np < 8; np++) {
                const uint32_t bo = bvo + np * 16 * 144 + j * 32;
                uint32_t bh0, bh1, bh2, bh3, bl0, bl1, bl2, bl3;
                ldmx4(bh0, bh1, bh2, bh3, sk + F3_VHI + bo);
                ldmx4(bl0, bl1, bl2, bl3, sk + F3_VLO + bo);
                float* o0 = oacc[np * 2];
                float* o1 = oacc[np * 2 + 1];
                mma_bf16(o0[0], o0[1], o0[2], o0[3], aph[0], aph[1], aph[2], aph[3], bh0, bh1);
                mma_bf16(o1[0], o1[1], o1[2], o1[3], aph[0], aph[1], aph[2], aph[3], bh2, bh3);
                mma_bf16(o0[0], o0[1], o0[2], o0[3], aph[0], aph[1], aph[2], aph[3], bl0, bl1);
                mma_bf16(o1[0], o1[1], o1[2], o1[3], aph[0], aph[1], aph[2], aph[3], bl2, bl3);
                mma_bf16(o0[0], o0[1], o0[2], o0[3], apl[0], apl[1], apl[2], apl[3], bh0, bh1);
                mma_bf16(o1[0], o1[1], o1[2], o1[3], apl[0], apl[1], apl[2], apl[3], bh2, bh3);
            }
        }

        if (kt + 1 < S_ / 64) cp_wait<0>();
        __syncthreads();
        buf ^= 1;
    }

    // ---- epilogue: write bf16 hi/lo directly ----
    const float i0 = 1.f / l0, i1 = 1.f / l1;
    const int r0g = q0r + w * 16 + (lane >> 2);
    const int col0 = h * 128 + ((lane & 3) << 1);
#pragma unroll
    for (int nt = 0; nt < 16; nt++) {
        const int col = col0 + nt * 8;
        const size_t idx0 = (size_t)(b * S_ + r0g) * E_ + col;
        const size_t idx1 = (size_t)(b * S_ + r0g + 8) * E_ + col;
        float f0 = oacc[nt][0] * i0, f1 = oacc[nt][1] * i0;
        float f2 = oacc[nt][2] * i1, f3 = oacc[nt][3] * i1;
        unsigned short ha, la, hbv, lb;
        split1(f0, ha, la); split1(f1, hbv, lb);
        *(ushort2*)&Ohi[idx0] = make_ushort2(ha, hbv);
        *(ushort2*)&Olo[idx0] = make_ushort2(la, lb);
        split1(f2, ha, la); split1(f3, hbv, lb);
        *(ushort2*)&Ohi[idx1] = make_ushort2(ha, hbv);
        *(ushort2*)&Olo[idx1] = make_ushort2(la, lb);
    }
}

// ================================ launch =====================================
extern "C" void kernel_launch(void* const* d_in, const int* in_sizes, int n_in,
                              void* d_out, int out_size) {
    const float* x   = (const float*)d_in[0];
    const float* Wq  = (const float*)d_in[1];
    const float* bq  = (const float*)d_in[2];
    const float* Wkv = (const float*)d_in[3];
    const float* bkv = (const float*)d_in[4];
    const float* Wo  = (const float*)d_in[5];
    float* out = (float*)d_out;

    float *qb, *kvb;
    cudaGetSymbolAddress((void**)&qb,  g_qproj);
    cudaGetSymbolAddress((void**)&kvb, g_kvproj);
    unsigned short *xhi, *xlo, *wqhi, *wqlo, *wkvhi, *wkvlo, *wohi, *wolo, *aohi, *aolo;
    unsigned short *vthi, *vtlo;
    signed char *q1, *q0, *k1, *k0;
    float *qs2, *ksc;
    cudaGetSymbolAddress((void**)&xhi,  g_xhi);
    cudaGetSymbolAddress((void**)&xlo,  g_xlo);
    cudaGetSymbolAddress((void**)&wqhi, g_wqhi);
    cudaGetSymbolAddress((void**)&wqlo, g_wqlo);
    cudaGetSymbolAddress((void**)&wkvhi, g_wkvhi);
    cudaGetSymbolAddress((void**)&wkvlo, g_wkvlo);
    cudaGetSymbolAddress((void**)&wohi, g_wohi);
    cudaGetSymbolAddress((void**)&wolo, g_wolo);
    cudaGetSymbolAddress((void**)&aohi, g_aohi);
    cudaGetSymbolAddress((void**)&aolo, g_aolo);
    cudaGetSymbolAddress((void**)&vthi, g_vthi);
    cudaGetSymbolAddress((void**)&vtlo, g_vtlo);
    cudaGetSymbolAddress((void**)&q1,  g_q1);
    cudaGetSymbolAddress((void**)&q0,  g_q0);
    cudaGetSymbolAddress((void**)&k1,  g_k1);
    cudaGetSymbolAddress((void**)&k0,  g_k0);
    cudaGetSymbolAddress((void**)&qs2, g_qs2);
    cudaGetSymbolAddress((void**)&ksc, g_ksc);

    // fp32 -> bf16 hi/lo splits of input + weights
    {
        int n4;
        n4 = M_ * E_ / 4;   split_bf16<<<(n4 + 255) / 256, 256>>>(x,   xhi,  xlo,  n4);
        n4 = E_ * E_ / 4;   split_bf16<<<(n4 + 255) / 256, 256>>>(Wq,  wqhi, wqlo, n4);
        n4 = KVN_ * E_ / 4; split_bf16<<<(n4 + 255) / 256, 256>>>(Wkv, wkvhi, wkvlo, n4);
        n4 = E_ * E_ / 4;   split_bf16<<<(n4 + 255) / 256, 256>>>(Wo,  wohi, wolo, n4);
    }

    // Q / KV projections (fp32 out)
    gemm_hmma_x3<<<dim3(E_ / 128, M_ / 128), 256>>>(
        xhi, xlo, wqhi, wqlo, bq, qb, M_, E_, E_);
    gemm_hmma_x3<<<dim3(KVN_ / 128, M_ / 128), 256>>>(
        xhi, xlo, wkvhi, wkvlo, bkv, kvb, M_, KVN_, E_);

    // RoPE + int8 quantization (Q, K); V transpose + bf16 split
    rope_q_quant<<<M_ * H_ / 8, 256>>>(qb, q1, q0, qs2);
    rope_k_quant<<<M_ * KVH_ / 8, 256>>>(kvb, k1, k0, ksc);
    vtrans_split<<<dim3(S_ / 32, D_ / 32, B_ * KVH_), 256>>>(kvb, vthi, vtlo);

    // flash attention (int8 QK, bf16x3 PV; writes bf16 hi/lo directly)
    {
        cudaFuncSetAttribute(flash_hmma,
                             cudaFuncAttributeMaxDynamicSharedMemorySize, F3_SMEM);
        flash_hmma<<<dim3(S_ / 128, B_ * H_), 256, F3_SMEM>>>(
            q1, q0, k1, k0, vthi, vtlo, qs2, ksc, aohi, aolo);
    }

    // O projection
    gemm_hmma_x3<<<dim3(E_ / 128, M_ / 128), 256>>>(
        aohi, aolo, wohi, wolo, nullptr, out, M_, E_, E_);
}

// round 11
// speedup vs baseline: 1.4302x; 1.4302x over previous
#include <cuda_runtime.h>
#include <cuda_bf16.h>
#include <cuda_fp16.h>
#include <math.h>
#include <stdint.h>

// Problem constants
#define B_   2
#define S_   2048
#define E_   2048
#define H_   16
#define KVH_ 4
#define D_   128
#define M_   (B_ * S_)        // 4096 rows
#define KVN_ (2 * KVH_ * D_)  // 1024

// ---------------- scratch (device globals; no allocs allowed) ----------------
__device__ float g_qproj[(size_t)M_ * E_];
__device__ float g_kvproj[(size_t)M_ * KVN_];

__device__ unsigned short g_xhi[(size_t)M_ * E_];
__device__ unsigned short g_xlo[(size_t)M_ * E_];
__device__ unsigned short g_wqhi[(size_t)E_ * E_];
__device__ unsigned short g_wqlo[(size_t)E_ * E_];
__device__ unsigned short g_wkvhi[(size_t)KVN_ * E_];
__device__ unsigned short g_wkvlo[(size_t)KVN_ * E_];
__device__ unsigned short g_wohi[(size_t)E_ * E_];
__device__ unsigned short g_wolo[(size_t)E_ * E_];
__device__ unsigned short g_aohi[(size_t)M_ * E_];
__device__ unsigned short g_aolo[(size_t)M_ * E_];
// flash operands (Q/K bf16 hi/lo; V fp16 hi/lo transposed)
__device__ unsigned short g_qhi[(size_t)M_ * E_];
__device__ unsigned short g_qlo[(size_t)M_ * E_];
__device__ unsigned short g_kvphi[(size_t)M_ * KVN_];
__device__ unsigned short g_kvplo[(size_t)M_ * KVN_];
__device__ unsigned short g_vthi[(size_t)B_ * KVH_ * D_ * S_];
__device__ unsigned short g_vtlo[(size_t)B_ * KVH_ * D_ * S_];

// ============================ PTX helpers ====================================
__device__ __forceinline__ uint32_t smem_u32(const void* p) {
    uint32_t a;
    asm("{ .reg .u64 t; cvta.to.shared.u64 t, %1; cvt.u32.u64 %0, t; }"
        : "=r"(a) : "l"(p));
    return a;
}
__device__ __forceinline__ void cp_async16(uint32_t dst, const void* src) {
    asm volatile("cp.async.cg.shared.global [%0], [%1], 16;"
                 :: "r"(dst), "l"(src) : "memory");
}
__device__ __forceinline__ void cp_commit() {
    asm volatile("cp.async.commit_group;" ::: "memory");
}
template <int N>
__device__ __forceinline__ void cp_wait() {
    asm volatile("cp.async.wait_group %0;" :: "n"(N) : "memory");
}
__device__ __forceinline__ void ldmx4(uint32_t& r0, uint32_t& r1, uint32_t& r2,
                                      uint32_t& r3, uint32_t addr) {
    asm volatile("ldmatrix.sync.aligned.m8n8.x4.shared.b16 {%0,%1,%2,%3}, [%4];"
                 : "=r"(r0), "=r"(r1), "=r"(r2), "=r"(r3) : "r"(addr));
}
__device__ __forceinline__ void mma_bf16(float& d0, float& d1, float& d2, float& d3,
                                         uint32_t a0, uint32_t a1, uint32_t a2,
                                         uint32_t a3, uint32_t b0, uint32_t b1) {
    asm volatile(
        "mma.sync.aligned.m16n8k16.row.col.f32.bf16.bf16.f32 "
        "{%0,%1,%2,%3}, {%4,%5,%6,%7}, {%8,%9}, {%0,%1,%2,%3};"
        : "+f"(d0), "+f"(d1), "+f"(d2), "+f"(d3)
        : "r"(a0), "r"(a1), "r"(a2), "r"(a3), "r"(b0), "r"(b1));
}
__device__ __forceinline__ void mma_f16(float& d0, float& d1, float& d2, float& d3,
                                        uint32_t a0, uint32_t a1, uint32_t a2,
                                        uint32_t a3, uint32_t b0, uint32_t b1) {
    asm volatile(
        "mma.sync.aligned.m16n8k16.row.col.f32.f16.f16.f32 "
        "{%0,%1,%2,%3}, {%4,%5,%6,%7}, {%8,%9}, {%0,%1,%2,%3};"
        : "+f"(d0), "+f"(d1), "+f"(d2), "+f"(d3)
        : "r"(a0), "r"(a1), "r"(a2), "r"(a3), "r"(b0), "r"(b1));
}
__device__ __forceinline__ float ex2f(float x) {
    float y;
    asm("ex2.approx.ftz.f32 %0, %1;" : "=f"(y) : "f"(x));
    return y;
}
__device__ __forceinline__ uint32_t packhf(float a, float b) {
    __half2 t = __floats2half2_rn(a, b);
    return *(uint32_t*)&t;
}

// ====================== fp32 -> bf16 hi/lo split =============================
__device__ __forceinline__ void split1(float x, unsigned short& h, unsigned short& l) {
    __nv_bfloat16 bh = __float2bfloat16_rn(x);
    float r = x - __bfloat162float(bh);
    __nv_bfloat16 bl = __float2bfloat16_rn(r);
    h = __bfloat16_as_ushort(bh);
    l = __bfloat16_as_ushort(bl);
}
__global__ void __launch_bounds__(256) split_bf16(const float* __restrict__ in,
                                                  unsigned short* __restrict__ hi,
                                                  unsigned short* __restrict__ lo,
                                                  int n4) {
    int i = blockIdx.x * blockDim.x + threadIdx.x;
    if (i >= n4) return;
    float4 v = ((const float4*)in)[i];
    ushort4 h, l;
    split1(v.x, h.x, l.x);
    split1(v.y, h.y, l.y);
    split1(v.z, h.z, l.z);
    split1(v.w, h.w, l.w);
    ((ushort4*)hi)[i] = h;
    ((ushort4*)lo)[i] = l;
}

// ==================== RoPE fused with bf16 hi/lo split =======================
__global__ void __launch_bounds__(256)
rope_split(const float* __restrict__ t, unsigned short* __restrict__ hi,
           unsigned short* __restrict__ lo, int nHeads, int rowStride) {
    int idx = blockIdx.x * blockDim.x + threadIdx.x;
    int total = M_ * nHeads * 64;
    if (idx >= total) return;
    int i = idx & 63;
    int h = (idx >> 6) % nHeads;
    int m = idx / (64 * nHeads);
    int s = m & (S_ - 1);
    float inv = powf(10000.0f, -(float)i * (1.0f / 64.0f));
    float fr = (float)s * inv;
    float sn, cs;
    sincosf(fr, &sn, &cs);
    const float* p = t + (size_t)m * rowStride + h * 128 + i;
    float v1 = p[0], v2 = p[64];
    float o1 = v1 * cs - v2 * sn;
    float o2 = v2 * cs + v1 * sn;
    size_t o = (size_t)m * rowStride + h * 128 + i;
    unsigned short h1, l1, h2, l2;
    split1(o1, h1, l1);
    split1(o2, h2, l2);
    hi[o] = h1; lo[o] = l1;
    hi[o + 64] = h2; lo[o + 64] = l2;
}

// ========= V transpose + fp16 hi/lo split: kvproj V-part -> VT[d, s] =========
__global__ void __launch_bounds__(256) vtrans_split(const float* __restrict__ kv,
                                                    unsigned short* __restrict__ vthi,
                                                    unsigned short* __restrict__ vtlo) {
    __shared__ float t[32][33];
    const int s0 = blockIdx.x * 32, d0 = blockIdx.y * 32;
    const int bk = blockIdx.z;
    const int b = bk >> 2, kvh = bk & 3;
    const int tx = threadIdx.x & 31, ty = threadIdx.x >> 5;
#pragma unroll
    for (int i = 0; i < 4; i++) {
        int s = s0 + ty + i * 8;
        t[ty + i * 8][tx] =
            kv[(size_t)(b * S_ + s) * KVN_ + KVH_ * D_ + kvh * 128 + d0 + tx];
    }
    __syncthreads();
#pragma unroll
    for (int i = 0; i < 4; i++) {
        int d = d0 + ty + i * 8;
        float v = t[tx][ty + i * 8];
        __half hh = __float2half_rn(v);
        __half ll = __float2half_rn(v - __half2float(hh));
        size_t o = ((size_t)bk * 128 + d) * S_ + s0 + tx;
        vthi[o] = __half_as_ushort(hh);
        vtlo[o] = __half_as_ushort(ll);
    }
}

// =============== HMMA GEMM: C = A@W^T (+bias), 3x bf16 split =================
#define GS_STRIDE 80
#define GS_BUF    (128 * GS_STRIDE)

__global__ void __launch_bounds__(256)
gemm_hmma_x3(const unsigned short* __restrict__ Ahi, const unsigned short* __restrict__ Alo,
             const unsigned short* __restrict__ Bhi, const unsigned short* __restrict__ Blo,
             const float* __restrict__ bias, float* __restrict__ C,
             int M, int N, int K) {
    __shared__ __align__(16) unsigned char smem[4 * GS_BUF];
    const uint32_t sb = smem_u32(smem);
    const int tid = threadIdx.x;
    const int wid = tid >> 5, lane = tid & 31;
    const int wm = wid & 3;
    const int wn = wid >> 2;
    const int m0 = blockIdx.y * 128, n0 = blockIdx.x * 128;

    const int NCH = 3 * (K >> 5);
    const int segC = K >> 5;

    float acc[2][8][4];
#pragma unroll
    for (int mt = 0; mt < 2; mt++)
#pragma unroll
        for (int nt = 0; nt < 8; nt++)
#pragma unroll
            for (int i = 0; i < 4; i++) acc[mt][nt][i] = 0.f;

    auto issue = [&](int c, int buf) {
        const int seg = c / segC;
        const int kk = (c % segC) << 5;
        const unsigned short* Ap = (seg == 2) ? Alo : Ahi;
        const unsigned short* Bp = (seg == 1) ? Blo : Bhi;
#pragma unroll
        for (int h = 0; h < 2; h++) {
            const int u = tid + h * 256;
            const int row = u >> 2;
            const int kb = (u & 3) << 3;
            cp_async16(sb + buf * GS_BUF + row * GS_STRIDE + (kb << 1),
                       Ap + (size_t)(m0 + row) * K + kk + kb);
            cp_async16(sb + 2 * GS_BUF + buf * GS_BUF + row * GS_STRIDE + (kb << 1),
                       Bp + (size_t)(n0 + row) * K + kk + kb);
        }
        cp_commit();
    };

    issue(0, 0);
    int buf = 0;
    for (int c = 0; c < NCH; c++) {
        if (c + 1 < NCH) { issue(c + 1, buf ^ 1); cp_wait<1>(); }
        else             { cp_wait<0>(); }
        __syncthreads();

        const uint32_t abase = sb + buf * GS_BUF;
        const uint32_t bbase = sb + 2 * GS_BUF + buf * GS_BUF;
#pragma unroll
        for (int ks = 0; ks < 2; ks++) {
            const int kbyte = ks * 32;
            uint32_t a[2][4];
#pragma unroll
            for (int mt = 0; mt < 2; mt++) {
                const int row = wm * 32 + mt * 16 + (lane & 15);
                ldmx4(a[mt][0], a[mt][1], a[mt][2], a[mt][3],
                      abase + row * GS_STRIDE + kbyte + ((lane >> 4) << 4));
            }
            uint32_t b[8][2];
#pragma unroll
            for (int np = 0; np < 4; np++) {
                const int row = wn * 64 + np * 16 + (((lane >> 4) & 1) << 3) + (lane & 7);
                uint32_t r0, r1, r2, r3;
                ldmx4(r0, r1, r2, r3,
                      bbase + row * GS_STRIDE + kbyte + (((lane >> 3) & 1) << 4));
                b[np * 2][0] = r0; b[np * 2][1] = r1;
                b[np * 2 + 1][0] = r2; b[np * 2 + 1][1] = r3;
            }
#pragma unroll
            for (int mt = 0; mt < 2; mt++)
#pragma unroll
                for (int nt = 0; nt < 8; nt++)
                    mma_bf16(acc[mt][nt][0], acc[mt][nt][1],
                             acc[mt][nt][2], acc[mt][nt][3],
                             a[mt][0], a[mt][1], a[mt][2], a[mt][3],
                             b[nt][0], b[nt][1]);
        }
        __syncthreads();
        buf ^= 1;
    }

    const int mrow = m0 + wm * 32 + (lane >> 2);
    const int ncol0 = n0 + wn * 64 + ((lane & 3) << 1);
#pragma unroll
    for (int mt = 0; mt < 2; mt++) {
#pragma unroll
        for (int nt = 0; nt < 8; nt++) {
            const int n = ncol0 + nt * 8;
            float b0 = bias ? bias[n] : 0.f;
            float b1 = bias ? bias[n + 1] : 0.f;
            float2 v0 = make_float2(acc[mt][nt][0] + b0, acc[mt][nt][1] + b1);
            float2 v1 = make_float2(acc[mt][nt][2] + b0, acc[mt][nt][3] + b1);
            *(float2*)&C[(size_t)(mrow + mt * 16) * N + n] = v0;
            *(float2*)&C[(size_t)(mrow + mt * 16 + 8) * N + n] = v1;
        }
    }
}

// ========== flash attention: bf16x3 QK + fp16x2 PV (P single fp16) ===========
// CTA: 128 q rows, 8 warps. KV tile BN=64, double-buffered stages.
#define F2_QHI   0
#define F2_QLO   34816
#define F2_Q     69632
#define F2_STAGE 71680            // KHI 0 | KLO 17408 | VHI 34816 | VLO 53248
#define F2_SMEM  (F2_Q + 2 * F2_STAGE)   // 212992 B

__global__ void __launch_bounds__(256)
flash_hmma(const unsigned short* __restrict__ qhi, const unsigned short* __restrict__ qlo,
           const unsigned short* __restrict__ khi, const unsigned short* __restrict__ klo,
           const unsigned short* __restrict__ vthi, const unsigned short* __restrict__ vtlo,
           unsigned short* __restrict__ Ohi, unsigned short* __restrict__ Olo) {
    extern __shared__ __align__(16) unsigned char fsm2[];
    const uint32_t sb = smem_u32(fsm2);
    const int tid = threadIdx.x;
    const int w = tid >> 5, lane = tid & 31;
    const int bh = blockIdx.y;
    const int b = bh >> 4, h = bh & 15;
    const int kvh = h >> 2;
    const int q0 = blockIdx.x * 128;
    const float scale2 = 0.127518795f;    // (1/sqrt(128)) * log2(e)

    const unsigned short* qhp = qhi + (size_t)(b * S_ + q0) * E_ + h * 128;
    const unsigned short* qlp = qlo + (size_t)(b * S_ + q0) * E_ + h * 128;
    const unsigned short* khp = khi + (size_t)b * S_ * KVN_ + kvh * 128;
    const unsigned short* klp = klo + (size_t)b * S_ * KVN_ + kvh * 128;
    const unsigned short* vhp = vthi + ((size_t)(b * KVH_ + kvh) * 128) * S_;
    const unsigned short* vlp = vtlo + ((size_t)(b * KVH_ + kvh) * 128) * S_;

    auto load_q = [&](uint32_t dst, const unsigned short* src) {
#pragma unroll
        for (int it = 0; it < 8; it++) {
            int u = tid + it * 256;          // 128 rows x 256B
            int row = u >> 4;
            int cb = (u & 15) << 4;
            cp_async16(sb + dst + row * 272 + cb,
                       (const char*)src + (size_t)row * E_ * 2 + cb);
        }
    };
    auto load_k64 = [&](uint32_t dst, const unsigned short* src) {
#pragma unroll
        for (int it = 0; it < 4; it++) {
            int u = tid + it * 256;          // 64 rows x 256B
            int row = u >> 4;
            int cb = (u & 15) << 4;
            cp_async16(sb + dst + row * 272 + cb,
                       (const char*)src + (size_t)row * KVN_ * 2 + cb);
        }
    };
    auto load_v64 = [&](uint32_t dst, const unsigned short* src) {
#pragma unroll
        for (int it = 0; it < 4; it++) {
            int u = tid + it * 256;          // 128 rows x 128B
            int row = u >> 3;
            int cb = (u & 7) << 4;
            cp_async16(sb + dst + row * 144 + cb,
                       (const char*)src + (size_t)row * S_ * 2 + cb);
        }
    };
    auto issue_stage = [&](int stg, int kv0) {
        const uint32_t base = F2_Q + stg * F2_STAGE;
        load_k64(base,         khp + (size_t)kv0 * KVN_);
        load_k64(base + 17408, klp + (size_t)kv0 * KVN_);
        load_v64(base + 34816, vhp + kv0);
        load_v64(base + 53248, vlp + kv0);
        cp_commit();
    };

    // initial: Q + stage 0
    load_q(F2_QHI, qhp);
    load_q(F2_QLO, qlp);
    issue_stage(0, 0);
    cp_wait<0>();
    __syncthreads();

    float oacc[16][4];
#pragma unroll
    for (int nt = 0; nt < 16; nt++)
#pragma unroll
        for (int i = 0; i < 4; i++) oacc[nt][i] = 0.f;
    float m0 = -1e30f, m1 = -1e30f, l0 = 0.f, l1 = 0.f;

    const int arow = w * 16 + (lane & 15);
    const uint32_t aoff_base = arow * 272 + ((lane >> 4) << 4);
    const int brow = (((lane >> 4) & 1) << 3) + (lane & 7);
    const uint32_t bko = brow * 272 + (((lane >> 3) & 1) << 4);
    const uint32_t bvo = brow * 144 + (((lane >> 3) & 1) << 4);

    int buf = 0;
    for (int kt = 0; kt < S_ / 64; kt++) {
        if (kt + 1 < S_ / 64) issue_stage(buf ^ 1, (kt + 1) * 64);
        const uint32_t sk = sb + F2_Q + buf * F2_STAGE;

        float sacc[8][4];
#pragma unroll
        for (int nt = 0; nt < 8; nt++)
#pragma unroll
            for (int i = 0; i < 4; i++) sacc[nt][i] = 0.f;

        // ---- S = Q K^T (bf16 3-way split) ----
#pragma unroll
        for (int ks = 0; ks < 8; ks++) {
            uint32_t ah[4], al[4];
            ldmx4(ah[0], ah[1], ah[2], ah[3], sb + F2_QHI + aoff_base + ks * 32);
            ldmx4(al[0], al[1], al[2], al[3], sb + F2_QLO + aoff_base + ks * 32);
#pragma unroll
            for (int np = 0; np < 4; np++) {
                const uint32_t bo = bko + np * 16 * 272 + ks * 32;
                uint32_t bh0, bh1, bh2, bh3, bl0, bl1, bl2, bl3;
                ldmx4(bh0, bh1, bh2, bh3, sk + bo);
                ldmx4(bl0, bl1, bl2, bl3, sk + 17408 + bo);
                float* s0 = sacc[np * 2];
                float* s1 = sacc[np * 2 + 1];
                mma_bf16(s0[0], s0[1], s0[2], s0[3], ah[0], ah[1], ah[2], ah[3], bh0, bh1);
                mma_bf16(s1[0], s1[1], s1[2], s1[3], ah[0], ah[1], ah[2], ah[3], bh2, bh3);
                mma_bf16(s0[0], s0[1], s0[2], s0[3], ah[0], ah[1], ah[2], ah[3], bl0, bl1);
                mma_bf16(s1[0], s1[1], s1[2], s1[3], ah[0], ah[1], ah[2], ah[3], bl2, bl3);
                mma_bf16(s0[0], s0[1], s0[2], s0[3], al[0], al[1], al[2], al[3], bh0, bh1);
                mma_bf16(s1[0], s1[1], s1[2], s1[3], al[0], al[1], al[2], al[3], bh2, bh3);
            }
        }

        // ---- online softmax (exp2 domain) ----
        float mx0 = -1e30f, mx1 = -1e30f;
#pragma unroll
        for (int nt = 0; nt < 8; nt++) {
            sacc[nt][0] *= scale2; sacc[nt][1] *= scale2;
            sacc[nt][2] *= scale2; sacc[nt][3] *= scale2;
            mx0 = fmaxf(mx0, fmaxf(sacc[nt][0], sacc[nt][1]));
            mx1 = fmaxf(mx1, fmaxf(sacc[nt][2], sacc[nt][3]));
        }
        mx0 = fmaxf(mx0, __shfl_xor_sync(0xffffffffu, mx0, 1));
        mx0 = fmaxf(mx0, __shfl_xor_sync(0xffffffffu, mx0, 2));
        mx1 = fmaxf(mx1, __shfl_xor_sync(0xffffffffu, mx1, 1));
        mx1 = fmaxf(mx1, __shfl_xor_sync(0xffffffffu, mx1, 2));
        const float mn0 = fmaxf(m0, mx0), mn1 = fmaxf(m1, mx1);
        const float c0 = ex2f(m0 - mn0), c1 = ex2f(m1 - mn1);
        m0 = mn0; m1 = mn1;
        float sum0 = 0.f, sum1 = 0.f;
#pragma unroll
        for (int nt = 0; nt < 8; nt++) {
            sacc[nt][0] = ex2f(sacc[nt][0] - mn0);
            sacc[nt][1] = ex2f(sacc[nt][1] - mn0);
            sacc[nt][2] = ex2f(sacc[nt][2] - mn1);
            sacc[nt][3] = ex2f(sacc[nt][3] - mn1);
            sum0 += sacc[nt][0] + sacc[nt][1];
            sum1 += sacc[nt][2] + sacc[nt][3];
        }
#pragma unroll
        for (int nt = 0; nt < 16; nt++) {
            oacc[nt][0] *= c0; oacc[nt][1] *= c0;
            oacc[nt][2] *= c1; oacc[nt][3] *= c1;
        }
        sum0 += __shfl_xor_sync(0xffffffffu, sum0, 1);
        sum0 += __shfl_xor_sync(0xffffffffu, sum0, 2);
        sum1 += __shfl_xor_sync(0xffffffffu, sum1, 1);
        sum1 += __shfl_xor_sync(0xffffffffu, sum1, 2);
        l0 = l0 * c0 + sum0;
        l1 = l1 * c1 + sum1;

        // ---- O += P V (fp16: P single, V hi/lo) ----
#pragma unroll
        for (int j = 0; j < 4; j++) {
            const float* p0 = sacc[2 * j];
            const float* p1 = sacc[2 * j + 1];
            uint32_t ap[4];
            ap[0] = packhf(p0[0], p0[1]);
            ap[1] = packhf(p0[2], p0[3]);
            ap[2] = packhf(p1[0], p1[1]);
            ap[3] = packhf(p1[2], p1[3]);
#pragma unroll
            for (int np = 0; np < 8; np++) {
                const uint32_t bo = bvo + np * 16 * 144 + j * 32;
                uint32_t bh0, bh1, bh2, bh3, bl0, bl1, bl2, bl3;
                ldmx4(bh0, bh1, bh2, bh3, sk + 34816 + bo);
                ldmx4(bl0, bl1, bl2, bl3, sk + 53248 + bo);
                float* o0 = oacc[np * 2];
                float* o1 = oacc[np * 2 + 1];
                mma_f16(o0[0], o0[1], o0[2], o0[3], ap[0], ap[1], ap[2], ap[3], bh0, bh1);
                mma_f16(o1[0], o1[1], o1[2], o1[3], ap[0], ap[1], ap[2], ap[3], bh2, bh3);
                mma_f16(o0[0], o0[1], o0[2], o0[3], ap[0], ap[1], ap[2], ap[3], bl0, bl1);
                mma_f16(o1[0], o1[1], o1[2], o1[3], ap[0], ap[1], ap[2], ap[3], bl2, bl3);
            }
        }

        if (kt + 1 < S_ / 64) cp_wait<0>();
        __syncthreads();
        buf ^= 1;
    }

    // ---- epilogue: write bf16 hi/lo directly ----
    const float i0 = 1.f / l0, i1 = 1.f / l1;
    const int r0g = q0 + w * 16 + (lane >> 2);
    const int col0 = h * 128 + ((lane & 3) << 1);
#pragma unroll
    for (int nt = 0; nt < 16; nt++) {
        const int col = col0 + nt * 8;
        const size_t idx0 = (size_t)(b * S_ + r0g) * E_ + col;
        const size_t idx1 = (size_t)(b * S_ + r0g + 8) * E_ + col;
        float f0 = oacc[nt][0] * i0, f1 = oacc[nt][1] * i0;
        float f2 = oacc[nt][2] * i1, f3 = oacc[nt][3] * i1;
        unsigned short ha, la, hbv, lb;
        split1(f0, ha, la); split1(f1, hbv, lb);
        *(ushort2*)&Ohi[idx0] = make_ushort2(ha, hbv);
        *(ushort2*)&Olo[idx0] = make_ushort2(la, lb);
        split1(f2, ha, la); split1(f3, hbv, lb);
        *(ushort2*)&Ohi[idx1] = make_ushort2(ha, hbv);
        *(ushort2*)&Olo[idx1] = make_ushort2(la, lb);
    }
}

// ================================ launch =====================================
extern "C" void kernel_launch(void* const* d_in, const int* in_sizes, int n_in,
                              void* d_out, int out_size) {
    const float* x   = (const float*)d_in[0];
    const float* Wq  = (const float*)d_in[1];
    const float* bq  = (const float*)d_in[2];
    const float* Wkv = (const float*)d_in[3];
    const float* bkv = (const float*)d_in[4];
    const float* Wo  = (const float*)d_in[5];
    float* out = (float*)d_out;

    float *qb, *kvb;
    cudaGetSymbolAddress((void**)&qb,  g_qproj);
    cudaGetSymbolAddress((void**)&kvb, g_kvproj);
    unsigned short *xhi, *xlo, *wqhi, *wqlo, *wkvhi, *wkvlo, *wohi, *wolo, *aohi, *aolo;
    unsigned short *qhi, *qlo, *kvphi, *kvplo, *vthi, *vtlo;
    cudaGetSymbolAddress((void**)&xhi,  g_xhi);
    cudaGetSymbolAddress((void**)&xlo,  g_xlo);
    cudaGetSymbolAddress((void**)&wqhi, g_wqhi);
    cudaGetSymbolAddress((void**)&wqlo, g_wqlo);
    cudaGetSymbolAddress((void**)&wkvhi, g_wkvhi);
    cudaGetSymbolAddress((void**)&wkvlo, g_wkvlo);
    cudaGetSymbolAddress((void**)&wohi, g_wohi);
    cudaGetSymbolAddress((void**)&wolo, g_wolo);
    cudaGetSymbolAddress((void**)&aohi, g_aohi);
    cudaGetSymbolAddress((void**)&aolo, g_aolo);
    cudaGetSymbolAddress((void**)&qhi,  g_qhi);
    cudaGetSymbolAddress((void**)&qlo,  g_qlo);
    cudaGetSymbolAddress((void**)&kvphi, g_kvphi);
    cudaGetSymbolAddress((void**)&kvplo, g_kvplo);
    cudaGetSymbolAddress((void**)&vthi, g_vthi);
    cudaGetSymbolAddress((void**)&vtlo, g_vtlo);

    // fp32 -> bf16 hi/lo splits of input + weights
    {
        int n4;
        n4 = M_ * E_ / 4;   split_bf16<<<(n4 + 255) / 256, 256>>>(x,   xhi,  xlo,  n4);
        n4 = E_ * E_ / 4;   split_bf16<<<(n4 + 255) / 256, 256>>>(Wq,  wqhi, wqlo, n4);
        n4 = KVN_ * E_ / 4; split_bf16<<<(n4 + 255) / 256, 256>>>(Wkv, wkvhi, wkvlo, n4);
        n4 = E_ * E_ / 4;   split_bf16<<<(n4 + 255) / 256, 256>>>(Wo,  wohi, wolo, n4);
    }

    // Q / KV projections (fp32 out)
    gemm_hmma_x3<<<dim3(E_ / 128, M_ / 128), 256>>>(
        xhi, xlo, wqhi, wqlo, bq, qb, M_, E_, E_);
    gemm_hmma_x3<<<dim3(KVN_ / 128, M_ / 128), 256>>>(
        xhi, xlo, wkvhi, wkvlo, bkv, kvb, M_, KVN_, E_);

    // RoPE fused with split (Q, K); V transpose+split (fp16)
    {
        int totq = M_ * H_ * 64;
        rope_split<<<(totq + 255) / 256, 256>>>(qb, qhi, qlo, H_, E_);
        int totk = M_ * KVH_ * 64;
        rope_split<<<(totk + 255) / 256, 256>>>(kvb, kvphi, kvplo, KVH_, KVN_);
        vtrans_split<<<dim3(S_ / 32, D_ / 32, B_ * KVH_), 256>>>(kvb, vthi, vtlo);
    }

    // flash attention (bf16x3 QK, fp16x2 PV; writes bf16 hi/lo directly)
    {
        cudaFuncSetAttribute(flash_hmma,
                             cudaFuncAttributeMaxDynamicSharedMemorySize, F2_SMEM);
        flash_hmma<<<dim3(S_ / 128, B_ * H_), 256, F2_SMEM>>>(
            qhi, qlo, kvphi, kvplo, vthi, vtlo, aohi, aolo);
    }

    // O projection
    gemm_hmma_x3<<<dim3(E_ / 128, M_ / 128), 256>>>(
        aohi, aolo, wohi, wolo, nullptr, out, M_, E_, E_);
}

// round 12
// speedup vs baseline: 1.5583x; 1.0896x over previous
#include <cuda_runtime.h>
#include <cuda_bf16.h>
#include <cuda_fp16.h>
#include <math.h>
#include <stdint.h>

// Problem constants
#define B_   2
#define S_   2048
#define E_   2048
#define H_   16
#define KVH_ 4
#define D_   128
#define M_   (B_ * S_)        // 4096 rows
#define KVN_ (2 * KVH_ * D_)  // 1024

// ---------------- scratch (device globals; no allocs allowed) ----------------
__device__ float g_qproj[(size_t)M_ * E_];
__device__ float g_kvproj[(size_t)M_ * KVN_];

__device__ unsigned short g_xhi[(size_t)M_ * E_];
__device__ unsigned short g_xlo[(size_t)M_ * E_];
__device__ unsigned short g_wqhi[(size_t)E_ * E_];
__device__ unsigned short g_wqlo[(size_t)E_ * E_];
__device__ unsigned short g_wkvhi[(size_t)KVN_ * E_];
__device__ unsigned short g_wkvlo[(size_t)KVN_ * E_];
__device__ unsigned short g_wohi[(size_t)E_ * E_];   // fp16 hi
__device__ unsigned short g_wolo[(size_t)E_ * E_];   // fp16 lo
__device__ unsigned short g_ahf[(size_t)M_ * E_];    // attention out, single fp16
// flash operands (Q/K bf16 hi/lo; V fp16 hi/lo transposed)
__device__ unsigned short g_qhi[(size_t)M_ * E_];
__device__ unsigned short g_qlo[(size_t)M_ * E_];
__device__ unsigned short g_kvphi[(size_t)M_ * KVN_];
__device__ unsigned short g_kvplo[(size_t)M_ * KVN_];
__device__ unsigned short g_vthi[(size_t)B_ * KVH_ * D_ * S_];
__device__ unsigned short g_vtlo[(size_t)B_ * KVH_ * D_ * S_];

// ============================ PTX helpers ====================================
__device__ __forceinline__ uint32_t smem_u32(const void* p) {
    uint32_t a;
    asm("{ .reg .u64 t; cvta.to.shared.u64 t, %1; cvt.u32.u64 %0, t; }"
        : "=r"(a) : "l"(p));
    return a;
}
__device__ __forceinline__ void cp_async16(uint32_t dst, const void* src) {
    asm volatile("cp.async.cg.shared.global [%0], [%1], 16;"
                 :: "r"(dst), "l"(src) : "memory");
}
__device__ __forceinline__ void cp_commit() {
    asm volatile("cp.async.commit_group;" ::: "memory");
}
template <int N>
__device__ __forceinline__ void cp_wait() {
    asm volatile("cp.async.wait_group %0;" :: "n"(N) : "memory");
}
__device__ __forceinline__ void ldmx4(uint32_t& r0, uint32_t& r1, uint32_t& r2,
                                      uint32_t& r3, uint32_t addr) {
    asm volatile("ldmatrix.sync.aligned.m8n8.x4.shared.b16 {%0,%1,%2,%3}, [%4];"
                 : "=r"(r0), "=r"(r1), "=r"(r2), "=r"(r3) : "r"(addr));
}
__device__ __forceinline__ void mma_bf16(float& d0, float& d1, float& d2, float& d3,
                                         uint32_t a0, uint32_t a1, uint32_t a2,
                                         uint32_t a3, uint32_t b0, uint32_t b1) {
    asm volatile(
        "mma.sync.aligned.m16n8k16.row.col.f32.bf16.bf16.f32 "
        "{%0,%1,%2,%3}, {%4,%5,%6,%7}, {%8,%9}, {%0,%1,%2,%3};"
        : "+f"(d0), "+f"(d1), "+f"(d2), "+f"(d3)
        : "r"(a0), "r"(a1), "r"(a2), "r"(a3), "r"(b0), "r"(b1));
}
__device__ __forceinline__ void mma_f16(float& d0, float& d1, float& d2, float& d3,
                                        uint32_t a0, uint32_t a1, uint32_t a2,
                                        uint32_t a3, uint32_t b0, uint32_t b1) {
    asm volatile(
        "mma.sync.aligned.m16n8k16.row.col.f32.f16.f16.f32 "
        "{%0,%1,%2,%3}, {%4,%5,%6,%7}, {%8,%9}, {%0,%1,%2,%3};"
        : "+f"(d0), "+f"(d1), "+f"(d2), "+f"(d3)
        : "r"(a0), "r"(a1), "r"(a2), "r"(a3), "r"(b0), "r"(b1));
}
__device__ __forceinline__ float ex2f(float x) {
    float y;
    asm("ex2.approx.ftz.f32 %0, %1;" : "=f"(y) : "f"(x));
    return y;
}
__device__ __forceinline__ uint32_t packhf(float a, float b) {
    __half2 t = __floats2half2_rn(a, b);
    return *(uint32_t*)&t;
}

// ====================== fp32 -> bf16 hi/lo split =============================
__device__ __forceinline__ void split1(float x, unsigned short& h, unsigned short& l) {
    __nv_bfloat16 bh = __float2bfloat16_rn(x);
    float r = x - __bfloat162float(bh);
    __nv_bfloat16 bl = __float2bfloat16_rn(r);
    h = __bfloat16_as_ushort(bh);
    l = __bfloat16_as_ushort(bl);
}
__global__ void __launch_bounds__(256) split_bf16(const float* __restrict__ in,
                                                  unsigned short* __restrict__ hi,
                                                  unsigned short* __restrict__ lo,
                                                  int n4) {
    int i = blockIdx.x * blockDim.x + threadIdx.x;
    if (i >= n4) return;
    float4 v = ((const float4*)in)[i];
    ushort4 h, l;
    split1(v.x, h.x, l.x);
    split1(v.y, h.y, l.y);
    split1(v.z, h.z, l.z);
    split1(v.w, h.w, l.w);
    ((ushort4*)hi)[i] = h;
    ((ushort4*)lo)[i] = l;
}

// ====================== fp32 -> fp16 hi/lo split =============================
__device__ __forceinline__ void split1h(float x, unsigned short& h, unsigned short& l) {
    __half hh = __float2half_rn(x);
    __half ll = __float2half_rn(x - __half2float(hh));
    h = __half_as_ushort(hh);
    l = __half_as_ushort(ll);
}
__global__ void __launch_bounds__(256) split_fp16(const float* __restrict__ in,
                                                  unsigned short* __restrict__ hi,
                                                  unsigned short* __restrict__ lo,
                                                  int n4) {
    int i = blockIdx.x * blockDim.x + threadIdx.x;
    if (i >= n4) return;
    float4 v = ((const float4*)in)[i];
    ushort4 h, l;
    split1h(v.x, h.x, l.x);
    split1h(v.y, h.y, l.y);
    split1h(v.z, h.z, l.z);
    split1h(v.w, h.w, l.w);
    ((ushort4*)hi)[i] = h;
    ((ushort4*)lo)[i] = l;
}

// ==================== RoPE fused with bf16 hi/lo split =======================
__global__ void __launch_bounds__(256)
rope_split(const float* __restrict__ t, unsigned short* __restrict__ hi,
           unsigned short* __restrict__ lo, int nHeads, int rowStride) {
    int idx = blockIdx.x * blockDim.x + threadIdx.x;
    int total = M_ * nHeads * 64;
    if (idx >= total) return;
    int i = idx & 63;
    int h = (idx >> 6) % nHeads;
    int m = idx / (64 * nHeads);
    int s = m & (S_ - 1);
    float inv = powf(10000.0f, -(float)i * (1.0f / 64.0f));
    float fr = (float)s * inv;
    float sn, cs;
    sincosf(fr, &sn, &cs);
    const float* p = t + (size_t)m * rowStride + h * 128 + i;
    float v1 = p[0], v2 = p[64];
    float o1 = v1 * cs - v2 * sn;
    float o2 = v2 * cs + v1 * sn;
    size_t o = (size_t)m * rowStride + h * 128 + i;
    unsigned short h1, l1, h2, l2;
    split1(o1, h1, l1);
    split1(o2, h2, l2);
    hi[o] = h1; lo[o] = l1;
    hi[o + 64] = h2; lo[o + 64] = l2;
}

// ========= V transpose + fp16 hi/lo split: kvproj V-part -> VT[d, s] =========
__global__ void __launch_bounds__(256) vtrans_split(const float* __restrict__ kv,
                                                    unsigned short* __restrict__ vthi,
                                                    unsigned short* __restrict__ vtlo) {
    __shared__ float t[32][33];
    const int s0 = blockIdx.x * 32, d0 = blockIdx.y * 32;
    const int bk = blockIdx.z;
    const int b = bk >> 2, kvh = bk & 3;
    const int tx = threadIdx.x & 31, ty = threadIdx.x >> 5;
#pragma unroll
    for (int i = 0; i < 4; i++) {
        int s = s0 + ty + i * 8;
        t[ty + i * 8][tx] =
            kv[(size_t)(b * S_ + s) * KVN_ + KVH_ * D_ + kvh * 128 + d0 + tx];
    }
    __syncthreads();
#pragma unroll
    for (int i = 0; i < 4; i++) {
        int d = d0 + ty + i * 8;
        float v = t[tx][ty + i * 8];
        unsigned short hh, ll;
        split1h(v, hh, ll);
        size_t o = ((size_t)bk * 128 + d) * S_ + s0 + tx;
        vthi[o] = hh;
        vtlo[o] = ll;
    }
}

// =============== HMMA GEMM: C = A@W^T (+bias), 3x bf16 split =================
#define GS_STRIDE 80
#define GS_BUF    (128 * GS_STRIDE)

__global__ void __launch_bounds__(256)
gemm_hmma_x3(const unsigned short* __restrict__ Ahi, const unsigned short* __restrict__ Alo,
             const unsigned short* __restrict__ Bhi, const unsigned short* __restrict__ Blo,
             const float* __restrict__ bias, float* __restrict__ C,
             int M, int N, int K) {
    __shared__ __align__(16) unsigned char smem[4 * GS_BUF];
    const uint32_t sb = smem_u32(smem);
    const int tid = threadIdx.x;
    const int wid = tid >> 5, lane = tid & 31;
    const int wm = wid & 3;
    const int wn = wid >> 2;
    const int m0 = blockIdx.y * 128, n0 = blockIdx.x * 128;

    const int NCH = 3 * (K >> 5);
    const int segC = K >> 5;

    float acc[2][8][4];
#pragma unroll
    for (int mt = 0; mt < 2; mt++)
#pragma unroll
        for (int nt = 0; nt < 8; nt++)
#pragma unroll
            for (int i = 0; i < 4; i++) acc[mt][nt][i] = 0.f;

    auto issue = [&](int c, int buf) {
        const int seg = c / segC;
        const int kk = (c % segC) << 5;
        const unsigned short* Ap = (seg == 2) ? Alo : Ahi;
        const unsigned short* Bp = (seg == 1) ? Blo : Bhi;
#pragma unroll
        for (int h = 0; h < 2; h++) {
            const int u = tid + h * 256;
            const int row = u >> 2;
            const int kb = (u & 3) << 3;
            cp_async16(sb + buf * GS_BUF + row * GS_STRIDE + (kb << 1),
                       Ap + (size_t)(m0 + row) * K + kk + kb);
            cp_async16(sb + 2 * GS_BUF + buf * GS_BUF + row * GS_STRIDE + (kb << 1),
                       Bp + (size_t)(n0 + row) * K + kk + kb);
        }
        cp_commit();
    };

    issue(0, 0);
    int buf = 0;
    for (int c = 0; c < NCH; c++) {
        if (c + 1 < NCH) { issue(c + 1, buf ^ 1); cp_wait<1>(); }
        else             { cp_wait<0>(); }
        __syncthreads();

        const uint32_t abase = sb + buf * GS_BUF;
        const uint32_t bbase = sb + 2 * GS_BUF + buf * GS_BUF;
#pragma unroll
        for (int ks = 0; ks < 2; ks++) {
            const int kbyte = ks * 32;
            uint32_t a[2][4];
#pragma unroll
            for (int mt = 0; mt < 2; mt++) {
                const int row = wm * 32 + mt * 16 + (lane & 15);
                ldmx4(a[mt][0], a[mt][1], a[mt][2], a[mt][3],
                      abase + row * GS_STRIDE + kbyte + ((lane >> 4) << 4));
            }
            uint32_t b[8][2];
#pragma unroll
            for (int np = 0; np < 4; np++) {
                const int row = wn * 64 + np * 16 + (((lane >> 4) & 1) << 3) + (lane & 7);
                uint32_t r0, r1, r2, r3;
                ldmx4(r0, r1, r2, r3,
                      bbase + row * GS_STRIDE + kbyte + (((lane >> 3) & 1) << 4));
                b[np * 2][0] = r0; b[np * 2][1] = r1;
                b[np * 2 + 1][0] = r2; b[np * 2 + 1][1] = r3;
            }
#pragma unroll
            for (int mt = 0; mt < 2; mt++)
#pragma unroll
                for (int nt = 0; nt < 8; nt++)
                    mma_bf16(acc[mt][nt][0], acc[mt][nt][1],
                             acc[mt][nt][2], acc[mt][nt][3],
                             a[mt][0], a[mt][1], a[mt][2], a[mt][3],
                             b[nt][0], b[nt][1]);
        }
        __syncthreads();
        buf ^= 1;
    }

    const int mrow = m0 + wm * 32 + (lane >> 2);
    const int ncol0 = n0 + wn * 64 + ((lane & 3) << 1);
#pragma unroll
    for (int mt = 0; mt < 2; mt++) {
#pragma unroll
        for (int nt = 0; nt < 8; nt++) {
            const int n = ncol0 + nt * 8;
            float b0 = bias ? bias[n] : 0.f;
            float b1 = bias ? bias[n + 1] : 0.f;
            float2 v0 = make_float2(acc[mt][nt][0] + b0, acc[mt][nt][1] + b1);
            float2 v1 = make_float2(acc[mt][nt][2] + b0, acc[mt][nt][3] + b1);
            *(float2*)&C[(size_t)(mrow + mt * 16) * N + n] = v0;
            *(float2*)&C[(size_t)(mrow + mt * 16 + 8) * N + n] = v1;
        }
    }
}

// ====== fp16 GEMM: C = A@W^T, A single fp16, W fp16 hi/lo (2 segments) =======
__global__ void __launch_bounds__(256)
gemm_hf_x2(const unsigned short* __restrict__ Ahf,
           const unsigned short* __restrict__ Bhi, const unsigned short* __restrict__ Blo,
           float* __restrict__ C, int M, int N, int K) {
    __shared__ __align__(16) unsigned char smem[4 * GS_BUF];
    const uint32_t sb = smem_u32(smem);
    const int tid = threadIdx.x;
    const int wid = tid >> 5, lane = tid & 31;
    const int wm = wid & 3;
    const int wn = wid >> 2;
    const int m0 = blockIdx.y * 128, n0 = blockIdx.x * 128;

    const int NCH = 2 * (K >> 5);
    const int segC = K >> 5;

    float acc[2][8][4];
#pragma unroll
    for (int mt = 0; mt < 2; mt++)
#pragma unroll
        for (int nt = 0; nt < 8; nt++)
#pragma unroll
            for (int i = 0; i < 4; i++) acc[mt][nt][i] = 0.f;

    auto issue = [&](int c, int buf) {
        const int seg = c / segC;
        const int kk = (c % segC) << 5;
        const unsigned short* Bp = seg ? Blo : Bhi;
#pragma unroll
        for (int h = 0; h < 2; h++) {
            const int u = tid + h * 256;
            const int row = u >> 2;
            const int kb = (u & 3) << 3;
            cp_async16(sb + buf * GS_BUF + row * GS_STRIDE + (kb << 1),
                       Ahf + (size_t)(m0 + row) * K + kk + kb);
            cp_async16(sb + 2 * GS_BUF + buf * GS_BUF + row * GS_STRIDE + (kb << 1),
                       Bp + (size_t)(n0 + row) * K + kk + kb);
        }
        cp_commit();
    };

    issue(0, 0);
    int buf = 0;
    for (int c = 0; c < NCH; c++) {
        if (c + 1 < NCH) { issue(c + 1, buf ^ 1); cp_wait<1>(); }
        else             { cp_wait<0>(); }
        __syncthreads();

        const uint32_t abase = sb + buf * GS_BUF;
        const uint32_t bbase = sb + 2 * GS_BUF + buf * GS_BUF;
#pragma unroll
        for (int ks = 0; ks < 2; ks++) {
            const int kbyte = ks * 32;
            uint32_t a[2][4];
#pragma unroll
            for (int mt = 0; mt < 2; mt++) {
                const int row = wm * 32 + mt * 16 + (lane & 15);
                ldmx4(a[mt][0], a[mt][1], a[mt][2], a[mt][3],
                      abase + row * GS_STRIDE + kbyte + ((lane >> 4) << 4));
            }
            uint32_t b[8][2];
#pragma unroll
            for (int np = 0; np < 4; np++) {
                const int row = wn * 64 + np * 16 + (((lane >> 4) & 1) << 3) + (lane & 7);
                uint32_t r0, r1, r2, r3;
                ldmx4(r0, r1, r2, r3,
                      bbase + row * GS_STRIDE + kbyte + (((lane >> 3) & 1) << 4));
                b[np * 2][0] = r0; b[np * 2][1] = r1;
                b[np * 2 + 1][0] = r2; b[np * 2 + 1][1] = r3;
            }
#pragma unroll
            for (int mt = 0; mt < 2; mt++)
#pragma unroll
                for (int nt = 0; nt < 8; nt++)
                    mma_f16(acc[mt][nt][0], acc[mt][nt][1],
                            acc[mt][nt][2], acc[mt][nt][3],
                            a[mt][0], a[mt][1], a[mt][2], a[mt][3],
                            b[nt][0], b[nt][1]);
        }
        __syncthreads();
        buf ^= 1;
    }

    const int mrow = m0 + wm * 32 + (lane >> 2);
    const int ncol0 = n0 + wn * 64 + ((lane & 3) << 1);
#pragma unroll
    for (int mt = 0; mt < 2; mt++) {
#pragma unroll
        for (int nt = 0; nt < 8; nt++) {
            const int n = ncol0 + nt * 8;
            float2 v0 = make_float2(acc[mt][nt][0], acc[mt][nt][1]);
            float2 v1 = make_float2(acc[mt][nt][2], acc[mt][nt][3]);
            *(float2*)&C[(size_t)(mrow + mt * 16) * N + n] = v0;
            *(float2*)&C[(size_t)(mrow + mt * 16 + 8) * N + n] = v1;
        }
    }
}

// ========== flash attention: bf16x3 QK + fp16x2 PV (P single fp16) ===========
// CTA: 128 q rows, 8 warps. KV tile BN=64, double-buffered stages.
#define F2_QHI   0
#define F2_QLO   34816
#define F2_Q     69632
#define F2_STAGE 71680            // KHI 0 | KLO 17408 | VHI 34816 | VLO 53248
#define F2_SMEM  (F2_Q + 2 * F2_STAGE)   // 212992 B

__global__ void __launch_bounds__(256)
flash_hmma(const unsigned short* __restrict__ qhi, const unsigned short* __restrict__ qlo,
           const unsigned short* __restrict__ khi, const unsigned short* __restrict__ klo,
           const unsigned short* __restrict__ vthi, const unsigned short* __restrict__ vtlo,
           unsigned short* __restrict__ Ohf) {
    extern __shared__ __align__(16) unsigned char fsm2[];
    const uint32_t sb = smem_u32(fsm2);
    const int tid = threadIdx.x;
    const int w = tid >> 5, lane = tid & 31;
    const int bh = blockIdx.y;
    const int b = bh >> 4, h = bh & 15;
    const int kvh = h >> 2;
    const int q0 = blockIdx.x * 128;
    const float scale2 = 0.127518795f;    // (1/sqrt(128)) * log2(e)

    const unsigned short* qhp = qhi + (size_t)(b * S_ + q0) * E_ + h * 128;
    const unsigned short* qlp = qlo + (size_t)(b * S_ + q0) * E_ + h * 128;
    const unsigned short* khp = khi + (size_t)b * S_ * KVN_ + kvh * 128;
    const unsigned short* klp = klo + (size_t)b * S_ * KVN_ + kvh * 128;
    const unsigned short* vhp = vthi + ((size_t)(b * KVH_ + kvh) * 128) * S_;
    const unsigned short* vlp = vtlo + ((size_t)(b * KVH_ + kvh) * 128) * S_;

    auto load_q = [&](uint32_t dst, const unsigned short* src) {
#pragma unroll
        for (int it = 0; it < 8; it++) {
            int u = tid + it * 256;          // 128 rows x 256B
            int row = u >> 4;
            int cb = (u & 15) << 4;
            cp_async16(sb + dst + row * 272 + cb,
                       (const char*)src + (size_t)row * E_ * 2 + cb);
        }
    };
    auto load_k64 = [&](uint32_t dst, const unsigned short* src) {
#pragma unroll
        for (int it = 0; it < 4; it++) {
            int u = tid + it * 256;          // 64 rows x 256B
            int row = u >> 4;
            int cb = (u & 15) << 4;
            cp_async16(sb + dst + row * 272 + cb,
                       (const char*)src + (size_t)row * KVN_ * 2 + cb);
        }
    };
    auto load_v64 = [&](uint32_t dst, const unsigned short* src) {
#pragma unroll
        for (int it = 0; it < 4; it++) {
            int u = tid + it * 256;          // 128 rows x 128B
            int row = u >> 3;
            int cb = (u & 7) << 4;
            cp_async16(sb + dst + row * 144 + cb,
                       (const char*)src + (size_t)row * S_ * 2 + cb);
        }
    };
    auto issue_stage = [&](int stg, int kv0) {
        const uint32_t base = F2_Q + stg * F2_STAGE;
        load_k64(base,         khp + (size_t)kv0 * KVN_);
        load_k64(base + 17408, klp + (size_t)kv0 * KVN_);
        load_v64(base + 34816, vhp + kv0);
        load_v64(base + 53248, vlp + kv0);
        cp_commit();
    };

    // initial: Q + stage 0
    load_q(F2_QHI, qhp);
    load_q(F2_QLO, qlp);
    issue_stage(0, 0);
    cp_wait<0>();
    __syncthreads();

    float oacc[16][4];
#pragma unroll
    for (int nt = 0; nt < 16; nt++)
#pragma unroll
        for (int i = 0; i < 4; i++) oacc[nt][i] = 0.f;
    float m0 = -1e30f, m1 = -1e30f, l0 = 0.f, l1 = 0.f;

    const int arow = w * 16 + (lane & 15);
    const uint32_t aoff_base = arow * 272 + ((lane >> 4) << 4);
    const int brow = (((lane >> 4) & 1) << 3) + (lane & 7);
    const uint32_t bko = brow * 272 + (((lane >> 3) & 1) << 4);
    const uint32_t bvo = brow * 144 + (((lane >> 3) & 1) << 4);

    int buf = 0;
    for (int kt = 0; kt < S_ / 64; kt++) {
        if (kt + 1 < S_ / 64) issue_stage(buf ^ 1, (kt + 1) * 64);
        const uint32_t sk = sb + F2_Q + buf * F2_STAGE;

        float sacc[8][4];
#pragma unroll
        for (int nt = 0; nt < 8; nt++)
#pragma unroll
            for (int i = 0; i < 4; i++) sacc[nt][i] = 0.f;

        // ---- S = Q K^T (bf16 3-way split) ----
#pragma unroll
        for (int ks = 0; ks < 8; ks++) {
            uint32_t ah[4], al[4];
            ldmx4(ah[0], ah[1], ah[2], ah[3], sb + F2_QHI + aoff_base + ks * 32);
            ldmx4(al[0], al[1], al[2], al[3], sb + F2_QLO + aoff_base + ks * 32);
#pragma unroll
            for (int np = 0; np < 4; np++) {
                const uint32_t bo = bko + np * 16 * 272 + ks * 32;
                uint32_t bh0, bh1, bh2, bh3, bl0, bl1, bl2, bl3;
                ldmx4(bh0, bh1, bh2, bh3, sk + bo);
                ldmx4(bl0, bl1, bl2, bl3, sk + 17408 + bo);
                float* s0 = sacc[np * 2];
                float* s1 = sacc[np * 2 + 1];
                mma_bf16(s0[0], s0[1], s0[2], s0[3], ah[0], ah[1], ah[2], ah[3], bh0, bh1);
                mma_bf16(s1[0], s1[1], s1[2], s1[3], ah[0], ah[1], ah[2], ah[3], bh2, bh3);
                mma_bf16(s0[0], s0[1], s0[2], s0[3], ah[0], ah[1], ah[2], ah[3], bl0, bl1);
                mma_bf16(s1[0], s1[1], s1[2], s1[3], ah[0], ah[1], ah[2], ah[3], bl2, bl3);
                mma_bf16(s0[0], s0[1], s0[2], s0[3], al[0], al[1], al[2], al[3], bh0, bh1);
                mma_bf16(s1[0], s1[1], s1[2], s1[3], al[0], al[1], al[2], al[3], bh2, bh3);
            }
        }

        // ---- online softmax (exp2 domain) ----
        float mx0 = -1e30f, mx1 = -1e30f;
#pragma unroll
        for (int nt = 0; nt < 8; nt++) {
            sacc[nt][0] *= scale2; sacc[nt][1] *= scale2;
            sacc[nt][2] *= scale2; sacc[nt][3] *= scale2;
            mx0 = fmaxf(mx0, fmaxf(sacc[nt][0], sacc[nt][1]));
            mx1 = fmaxf(mx1, fmaxf(sacc[nt][2], sacc[nt][3]));
        }
        mx0 = fmaxf(mx0, __shfl_xor_sync(0xffffffffu, mx0, 1));
        mx0 = fmaxf(mx0, __shfl_xor_sync(0xffffffffu, mx0, 2));
        mx1 = fmaxf(mx1, __shfl_xor_sync(0xffffffffu, mx1, 1));
        mx1 = fmaxf(mx1, __shfl_xor_sync(0xffffffffu, mx1, 2));
        const float mn0 = fmaxf(m0, mx0), mn1 = fmaxf(m1, mx1);
        const float c0 = ex2f(m0 - mn0), c1 = ex2f(m1 - mn1);
        m0 = mn0; m1 = mn1;
        float sum0 = 0.f, sum1 = 0.f;
#pragma unroll
        for (int nt = 0; nt < 8; nt++) {
            sacc[nt][0] = ex2f(sacc[nt][0] - mn0);
            sacc[nt][1] = ex2f(sacc[nt][1] - mn0);
            sacc[nt][2] = ex2f(sacc[nt][2] - mn1);
            sacc[nt][3] = ex2f(sacc[nt][3] - mn1);
            sum0 += sacc[nt][0] + sacc[nt][1];
            sum1 += sacc[nt][2] + sacc[nt][3];
        }
#pragma unroll
        for (int nt = 0; nt < 16; nt++) {
            oacc[nt][0] *= c0; oacc[nt][1] *= c0;
            oacc[nt][2] *= c1; oacc[nt][3] *= c1;
        }
        sum0 += __shfl_xor_sync(0xffffffffu, sum0, 1);
        sum0 += __shfl_xor_sync(0xffffffffu, sum0, 2);
        sum1 += __shfl_xor_sync(0xffffffffu, sum1, 1);
        sum1 += __shfl_xor_sync(0xffffffffu, sum1, 2);
        l0 = l0 * c0 + sum0;
        l1 = l1 * c1 + sum1;

        // ---- O += P V (fp16: P single, V hi/lo) ----
#pragma unroll
        for (int j = 0; j < 4; j++) {
            const float* p0 = sacc[2 * j];
            const float* p1 = sacc[2 * j + 1];
            uint32_t ap[4];
            ap[0] = packhf(p0[0], p0[1]);
            ap[1] = packhf(p0[2], p0[3]);
            ap[2] = packhf(p1[0], p1[1]);
            ap[3] = packhf(p1[2], p1[3]);
#pragma unroll
            for (int np = 0; np < 8; np++) {
                const uint32_t bo = bvo + np * 16 * 144 + j * 32;
                uint32_t bh0, bh1, bh2, bh3, bl0, bl1, bl2, bl3;
                ldmx4(bh0, bh1, bh2, bh3, sk + 34816 + bo);
                ldmx4(bl0, bl1, bl2, bl3, sk + 53248 + bo);
                float* o0 = oacc[np * 2];
                float* o1 = oacc[np * 2 + 1];
                mma_f16(o0[0], o0[1], o0[2], o0[3], ap[0], ap[1], ap[2], ap[3], bh0, bh1);
                mma_f16(o1[0], o1[1], o1[2], o1[3], ap[0], ap[1], ap[2], ap[3], bh2, bh3);
                mma_f16(o0[0], o0[1], o0[2], o0[3], ap[0], ap[1], ap[2], ap[3], bl0, bl1);
                mma_f16(o1[0], o1[1], o1[2], o1[3], ap[0], ap[1], ap[2], ap[3], bl2, bl3);
            }
        }

        if (kt + 1 < S_ / 64) cp_wait<0>();
        __syncthreads();
        buf ^= 1;
    }

    // ---- epilogue: write single fp16 ----
    const float i0 = 1.f / l0, i1 = 1.f / l1;
    const int r0g = q0 + w * 16 + (lane >> 2);
    const int col0 = h * 128 + ((lane & 3) << 1);
#pragma unroll
    for (int nt = 0; nt < 16; nt++) {
        const int col = col0 + nt * 8;
        const size_t idx0 = (size_t)(b * S_ + r0g) * E_ + col;
        const size_t idx1 = (size_t)(b * S_ + r0g + 8) * E_ + col;
        *(uint32_t*)&Ohf[idx0] = packhf(oacc[nt][0] * i0, oacc[nt][1] * i0);
        *(uint32_t*)&Ohf[idx1] = packhf(oacc[nt][2] * i1, oacc[nt][3] * i1);
    }
}

// ================================ launch =====================================
extern "C" void kernel_launch(void* const* d_in, const int* in_sizes, int n_in,
                              void* d_out, int out_size) {
    const float* x   = (const float*)d_in[0];
    const float* Wq  = (const float*)d_in[1];
    const float* bq  = (const float*)d_in[2];
    const float* Wkv = (const float*)d_in[3];
    const float* bkv = (const float*)d_in[4];
    const float* Wo  = (const float*)d_in[5];
    float* out = (float*)d_out;

    float *qb, *kvb;
    cudaGetSymbolAddress((void**)&qb,  g_qproj);
    cudaGetSymbolAddress((void**)&kvb, g_kvproj);
    unsigned short *xhi, *xlo, *wqhi, *wqlo, *wkvhi, *wkvlo, *wohi, *wolo, *ahf;
    unsigned short *qhi, *qlo, *kvphi, *kvplo, *vthi, *vtlo;
    cudaGetSymbolAddress((void**)&xhi,  g_xhi);
    cudaGetSymbolAddress((void**)&xlo,  g_xlo);
    cudaGetSymbolAddress((void**)&wqhi, g_wqhi);
    cudaGetSymbolAddress((void**)&wqlo, g_wqlo);
    cudaGetSymbolAddress((void**)&wkvhi, g_wkvhi);
    cudaGetSymbolAddress((void**)&wkvlo, g_wkvlo);
    cudaGetSymbolAddress((void**)&wohi, g_wohi);
    cudaGetSymbolAddress((void**)&wolo, g_wolo);
    cudaGetSymbolAddress((void**)&ahf,  g_ahf);
    cudaGetSymbolAddress((void**)&qhi,  g_qhi);
    cudaGetSymbolAddress((void**)&qlo,  g_qlo);
    cudaGetSymbolAddress((void**)&kvphi, g_kvphi);
    cudaGetSymbolAddress((void**)&kvplo, g_kvplo);
    cudaGetSymbolAddress((void**)&vthi, g_vthi);
    cudaGetSymbolAddress((void**)&vtlo, g_vtlo);

    // fp32 -> splits: x/Wq/Wkv bf16 hi/lo; Wo fp16 hi/lo
    {
        int n4;
        n4 = M_ * E_ / 4;   split_bf16<<<(n4 + 255) / 256, 256>>>(x,   xhi,  xlo,  n4);
        n4 = E_ * E_ / 4;   split_bf16<<<(n4 + 255) / 256, 256>>>(Wq,  wqhi, wqlo, n4);
        n4 = KVN_ * E_ / 4; split_bf16<<<(n4 + 255) / 256, 256>>>(Wkv, wkvhi, wkvlo, n4);
        n4 = E_ * E_ / 4;   split_fp16<<<(n4 + 255) / 256, 256>>>(Wo,  wohi, wolo, n4);
    }

    // Q / KV projections (fp32 out)
    gemm_hmma_x3<<<dim3(E_ / 128, M_ / 128), 256>>>(
        xhi, xlo, wqhi, wqlo, bq, qb, M_, E_, E_);
    gemm_hmma_x3<<<dim3(KVN_ / 128, M_ / 128), 256>>>(
        xhi, xlo, wkvhi, wkvlo, bkv, kvb, M_, KVN_, E_);

    // RoPE fused with split (Q, K); V transpose+split (fp16)
    {
        int totq = M_ * H_ * 64;
        rope_split<<<(totq + 255) / 256, 256>>>(qb, qhi, qlo, H_, E_);
        int totk = M_ * KVH_ * 64;
        rope_split<<<(totk + 255) / 256, 256>>>(kvb, kvphi, kvplo, KVH_, KVN_);
        vtrans_split<<<dim3(S_ / 32, D_ / 32, B_ * KVH_), 256>>>(kvb, vthi, vtlo);
    }

    // flash attention (bf16x3 QK, fp16x2 PV; writes single fp16 A)
    {
        cudaFuncSetAttribute(flash_hmma,
                             cudaFuncAttributeMaxDynamicSharedMemorySize, F2_SMEM);
        flash_hmma<<<dim3(S_ / 128, B_ * H_), 256, F2_SMEM>>>(
            qhi, qlo, kvphi, kvplo, vthi, vtlo, ahf);
    }

    // O projection: out = A @ Wo^T, fp16 2-term
    gemm_hf_x2<<<dim3(E_ / 128, M_ / 128), 256>>>(
        ahf, wohi, wolo, out, M_, E_, E_);
}

// round 13
// speedup vs baseline: 1.8696x; 1.1997x over previous
#include <cuda_runtime.h>
#include <cuda_bf16.h>
#include <cuda_fp16.h>
#include <math.h>
#include <stdint.h>

// Problem constants
#define B_   2
#define S_   2048
#define E_   2048
#define H_   16
#define KVH_ 4
#define D_   128
#define M_   (B_ * S_)        // 4096 rows
#define KVN_ (2 * KVH_ * D_)  // 1024

// ---------------- scratch (device globals; no allocs allowed) ----------------
__device__ float g_qproj[(size_t)M_ * E_];
__device__ float g_kvproj[(size_t)M_ * KVN_];

__device__ unsigned short g_xhf[(size_t)M_ * E_];    // x single fp16
__device__ unsigned short g_wqhi[(size_t)E_ * E_];   // fp16 hi/lo weights
__device__ unsigned short g_wqlo[(size_t)E_ * E_];
__device__ unsigned short g_wkvhi[(size_t)KVN_ * E_];
__device__ unsigned short g_wkvlo[(size_t)KVN_ * E_];
__device__ unsigned short g_wohi[(size_t)E_ * E_];
__device__ unsigned short g_wolo[(size_t)E_ * E_];
__device__ unsigned short g_ahf[(size_t)M_ * E_];    // attention out, single fp16
// flash operands
__device__ unsigned short g_qhf[(size_t)M_ * E_];    // rope'd Q, single fp16
__device__ unsigned short g_khi[(size_t)M_ * KVN_];  // rope'd K, fp16 hi/lo
__device__ unsigned short g_klo[(size_t)M_ * KVN_];
__device__ unsigned short g_vthi[(size_t)B_ * KVH_ * D_ * S_];  // V^T fp16 hi/lo
__device__ unsigned short g_vtlo[(size_t)B_ * KVH_ * D_ * S_];

// ============================ PTX helpers ====================================
__device__ __forceinline__ uint32_t smem_u32(const void* p) {
    uint32_t a;
    asm("{ .reg .u64 t; cvta.to.shared.u64 t, %1; cvt.u32.u64 %0, t; }"
        : "=r"(a) : "l"(p));
    return a;
}
__device__ __forceinline__ void cp_async16(uint32_t dst, const void* src) {
    asm volatile("cp.async.cg.shared.global [%0], [%1], 16;"
                 :: "r"(dst), "l"(src) : "memory");
}
__device__ __forceinline__ void cp_commit() {
    asm volatile("cp.async.commit_group;" ::: "memory");
}
template <int N>
__device__ __forceinline__ void cp_wait() {
    asm volatile("cp.async.wait_group %0;" :: "n"(N) : "memory");
}
__device__ __forceinline__ void ldmx4(uint32_t& r0, uint32_t& r1, uint32_t& r2,
                                      uint32_t& r3, uint32_t addr) {
    asm volatile("ldmatrix.sync.aligned.m8n8.x4.shared.b16 {%0,%1,%2,%3}, [%4];"
                 : "=r"(r0), "=r"(r1), "=r"(r2), "=r"(r3) : "r"(addr));
}
__device__ __forceinline__ void mma_f16(float& d0, float& d1, float& d2, float& d3,
                                        uint32_t a0, uint32_t a1, uint32_t a2,
                                        uint32_t a3, uint32_t b0, uint32_t b1) {
    asm volatile(
        "mma.sync.aligned.m16n8k16.row.col.f32.f16.f16.f32 "
        "{%0,%1,%2,%3}, {%4,%5,%6,%7}, {%8,%9}, {%0,%1,%2,%3};"
        : "+f"(d0), "+f"(d1), "+f"(d2), "+f"(d3)
        : "r"(a0), "r"(a1), "r"(a2), "r"(a3), "r"(b0), "r"(b1));
}
__device__ __forceinline__ float ex2f(float x) {
    float y;
    asm("ex2.approx.ftz.f32 %0, %1;" : "=f"(y) : "f"(x));
    return y;
}
__device__ __forceinline__ uint32_t packhf(float a, float b) {
    __half2 t = __floats2half2_rn(a, b);
    return *(uint32_t*)&t;
}

// ====================== fp32 -> fp16 conversions =============================
__device__ __forceinline__ void split1h(float x, unsigned short& h, unsigned short& l) {
    __half hh = __float2half_rn(x);
    __half ll = __float2half_rn(x - __half2float(hh));
    h = __half_as_ushort(hh);
    l = __half_as_ushort(ll);
}
__global__ void __launch_bounds__(256) split_fp16(const float* __restrict__ in,
                                                  unsigned short* __restrict__ hi,
                                                  unsigned short* __restrict__ lo,
                                                  int n4) {
    int i = blockIdx.x * blockDim.x + threadIdx.x;
    if (i >= n4) return;
    float4 v = ((const float4*)in)[i];
    ushort4 h, l;
    split1h(v.x, h.x, l.x);
    split1h(v.y, h.y, l.y);
    split1h(v.z, h.z, l.z);
    split1h(v.w, h.w, l.w);
    ((ushort4*)hi)[i] = h;
    ((ushort4*)lo)[i] = l;
}
__global__ void __launch_bounds__(256) to_fp16(const float* __restrict__ in,
                                               unsigned short* __restrict__ outp,
                                               int n4) {
    int i = blockIdx.x * blockDim.x + threadIdx.x;
    if (i >= n4) return;
    float4 v = ((const float4*)in)[i];
    ushort4 h;
    h.x = __half_as_ushort(__float2half_rn(v.x));
    h.y = __half_as_ushort(__float2half_rn(v.y));
    h.z = __half_as_ushort(__float2half_rn(v.z));
    h.w = __half_as_ushort(__float2half_rn(v.w));
    ((ushort4*)outp)[i] = h;
}

// ==================== RoPE: Q -> single fp16 =================================
__global__ void __launch_bounds__(256)
rope_q_f16(const float* __restrict__ t, unsigned short* __restrict__ qhf) {
    int idx = blockIdx.x * blockDim.x + threadIdx.x;
    int total = M_ * H_ * 64;
    if (idx >= total) return;
    int i = idx & 63;
    int h = (idx >> 6) % H_;
    int m = idx / (64 * H_);
    int s = m & (S_ - 1);
    float inv = powf(10000.0f, -(float)i * (1.0f / 64.0f));
    float fr = (float)s * inv;
    float sn, cs;
    sincosf(fr, &sn, &cs);
    const float* p = t + (size_t)m * E_ + h * 128 + i;
    float v1 = p[0], v2 = p[64];
    size_t o = (size_t)m * E_ + h * 128 + i;
    qhf[o]      = __half_as_ushort(__float2half_rn(v1 * cs - v2 * sn));
    qhf[o + 64] = __half_as_ushort(__float2half_rn(v2 * cs + v1 * sn));
}

// ==================== RoPE: K -> fp16 hi/lo ==================================
__global__ void __launch_bounds__(256)
rope_k_f16hl(const float* __restrict__ t, unsigned short* __restrict__ hi,
             unsigned short* __restrict__ lo) {
    int idx = blockIdx.x * blockDim.x + threadIdx.x;
    int total = M_ * KVH_ * 64;
    if (idx >= total) return;
    int i = idx & 63;
    int h = (idx >> 6) % KVH_;
    int m = idx / (64 * KVH_);
    int s = m & (S_ - 1);
    float inv = powf(10000.0f, -(float)i * (1.0f / 64.0f));
    float fr = (float)s * inv;
    float sn, cs;
    sincosf(fr, &sn, &cs);
    const float* p = t + (size_t)m * KVN_ + h * 128 + i;
    float v1 = p[0], v2 = p[64];
    float o1 = v1 * cs - v2 * sn;
    float o2 = v2 * cs + v1 * sn;
    size_t o = (size_t)m * KVN_ + h * 128 + i;
    unsigned short h1, l1, h2, l2;
    split1h(o1, h1, l1);
    split1h(o2, h2, l2);
    hi[o] = h1; lo[o] = l1;
    hi[o + 64] = h2; lo[o + 64] = l2;
}

// ========= V transpose + fp16 hi/lo split: kvproj V-part -> VT[d, s] =========
__global__ void __launch_bounds__(256) vtrans_split(const float* __restrict__ kv,
                                                    unsigned short* __restrict__ vthi,
                                                    unsigned short* __restrict__ vtlo) {
    __shared__ float t[32][33];
    const int s0 = blockIdx.x * 32, d0 = blockIdx.y * 32;
    const int bk = blockIdx.z;
    const int b = bk >> 2, kvh = bk & 3;
    const int tx = threadIdx.x & 31, ty = threadIdx.x >> 5;
#pragma unroll
    for (int i = 0; i < 4; i++) {
        int s = s0 + ty + i * 8;
        t[ty + i * 8][tx] =
            kv[(size_t)(b * S_ + s) * KVN_ + KVH_ * D_ + kvh * 128 + d0 + tx];
    }
    __syncthreads();
#pragma unroll
    for (int i = 0; i < 4; i++) {
        int d = d0 + ty + i * 8;
        float v = t[tx][ty + i * 8];
        unsigned short hh, ll;
        split1h(v, hh, ll);
        size_t o = ((size_t)bk * 128 + d) * S_ + s0 + tx;
        vthi[o] = hh;
        vtlo[o] = ll;
    }
}

// ====== fp16 GEMM: C = A@W^T (+bias), A single fp16, W fp16 hi/lo ============
#define GS_STRIDE 80
#define GS_BUF    (128 * GS_STRIDE)

__global__ void __launch_bounds__(256)
gemm_hf_x2(const unsigned short* __restrict__ Ahf,
           const unsigned short* __restrict__ Bhi, const unsigned short* __restrict__ Blo,
           const float* __restrict__ bias, float* __restrict__ C,
           int M, int N, int K) {
    __shared__ __align__(16) unsigned char smem[4 * GS_BUF];
    const uint32_t sb = smem_u32(smem);
    const int tid = threadIdx.x;
    const int wid = tid >> 5, lane = tid & 31;
    const int wm = wid & 3;
    const int wn = wid >> 2;
    const int m0 = blockIdx.y * 128, n0 = blockIdx.x * 128;

    const int NCH = 2 * (K >> 5);
    const int segC = K >> 5;

    float acc[2][8][4];
#pragma unroll
    for (int mt = 0; mt < 2; mt++)
#pragma unroll
        for (int nt = 0; nt < 8; nt++)
#pragma unroll
            for (int i = 0; i < 4; i++) acc[mt][nt][i] = 0.f;

    auto issue = [&](int c, int buf) {
        const int seg = c / segC;
        const int kk = (c % segC) << 5;
        const unsigned short* Bp = seg ? Blo : Bhi;
#pragma unroll
        for (int h = 0; h < 2; h++) {
            const int u = tid + h * 256;
            const int row = u >> 2;
            const int kb = (u & 3) << 3;
            cp_async16(sb + buf * GS_BUF + row * GS_STRIDE + (kb << 1),
                       Ahf + (size_t)(m0 + row) * K + kk + kb);
            cp_async16(sb + 2 * GS_BUF + buf * GS_BUF + row * GS_STRIDE + (kb << 1),
                       Bp + (size_t)(n0 + row) * K + kk + kb);
        }
        cp_commit();
    };

    issue(0, 0);
    int buf = 0;
    for (int c = 0; c < NCH; c++) {
        if (c + 1 < NCH) { issue(c + 1, buf ^ 1); cp_wait<1>(); }
        else             { cp_wait<0>(); }
        __syncthreads();

        const uint32_t abase = sb + buf * GS_BUF;
        const uint32_t bbase = sb + 2 * GS_BUF + buf * GS_BUF;
#pragma unroll
        for (int ks = 0; ks < 2; ks++) {
            const int kbyte = ks * 32;
            uint32_t a[2][4];
#pragma unroll
            for (int mt = 0; mt < 2; mt++) {
                const int row = wm * 32 + mt * 16 + (lane & 15);
                ldmx4(a[mt][0], a[mt][1], a[mt][2], a[mt][3],
                      abase + row * GS_STRIDE + kbyte + ((lane >> 4) << 4));
            }
            uint32_t b[8][2];
#pragma unroll
            for (int np = 0; np < 4; np++) {
                const int row = wn * 64 + np * 16 + (((lane >> 4) & 1) << 3) + (lane & 7);
                uint32_t r0, r1, r2, r3;
                ldmx4(r0, r1, r2, r3,
                      bbase + row * GS_STRIDE + kbyte + (((lane >> 3) & 1) << 4));
                b[np * 2][0] = r0; b[np * 2][1] = r1;
                b[np * 2 + 1][0] = r2; b[np * 2 + 1][1] = r3;
            }
#pragma unroll
            for (int mt = 0; mt < 2; mt++)
#pragma unroll
                for (int nt = 0; nt < 8; nt++)
                    mma_f16(acc[mt][nt][0], acc[mt][nt][1],
                            acc[mt][nt][2], acc[mt][nt][3],
                            a[mt][0], a[mt][1], a[mt][2], a[mt][3],
                            b[nt][0], b[nt][1]);
        }
        __syncthreads();
        buf ^= 1;
    }

    const int mrow = m0 + wm * 32 + (lane >> 2);
    const int ncol0 = n0 + wn * 64 + ((lane & 3) << 1);
#pragma unroll
    for (int mt = 0; mt < 2; mt++) {
#pragma unroll
        for (int nt = 0; nt < 8; nt++) {
            const int n = ncol0 + nt * 8;
            float b0 = bias ? bias[n] : 0.f;
            float b1 = bias ? bias[n + 1] : 0.f;
            float2 v0 = make_float2(acc[mt][nt][0] + b0, acc[mt][nt][1] + b1);
            float2 v1 = make_float2(acc[mt][nt][2] + b0, acc[mt][nt][3] + b1);
            *(float2*)&C[(size_t)(mrow + mt * 16) * N + n] = v0;
            *(float2*)&C[(size_t)(mrow + mt * 16 + 8) * N + n] = v1;
        }
    }
}

// ===== flash attention: fp16x2 QK (Q single, K hi/lo) + fp16x2 PV ============
// CTA: 128 q rows, 8 warps. KV tile BN=64, double-buffered stages.
#define F4_Q     0
#define F4_ST0   34816
#define F4_STAGE 71680            // KHI 0 | KLO 17408 | VHI 34816 | VLO 53248
#define F4_SMEM  (F4_ST0 + 2 * F4_STAGE)   // 178176 B

__global__ void __launch_bounds__(256)
flash_hmma(const unsigned short* __restrict__ qhf,
           const unsigned short* __restrict__ khi, const unsigned short* __restrict__ klo,
           const unsigned short* __restrict__ vthi, const unsigned short* __restrict__ vtlo,
           unsigned short* __restrict__ Ohf) {
    extern __shared__ __align__(16) unsigned char fsm2[];
    const uint32_t sb = smem_u32(fsm2);
    const int tid = threadIdx.x;
    const int w = tid >> 5, lane = tid & 31;
    const int bh = blockIdx.y;
    const int b = bh >> 4, h = bh & 15;
    const int kvh = h >> 2;
    const int q0 = blockIdx.x * 128;
    const float scale2 = 0.127518795f;    // (1/sqrt(128)) * log2(e)

    const unsigned short* qp  = qhf + (size_t)(b * S_ + q0) * E_ + h * 128;
    const unsigned short* khp = khi + (size_t)b * S_ * KVN_ + kvh * 128;
    const unsigned short* klp = klo + (size_t)b * S_ * KVN_ + kvh * 128;
    const unsigned short* vhp = vthi + ((size_t)(b * KVH_ + kvh) * 128) * S_;
    const unsigned short* vlp = vtlo + ((size_t)(b * KVH_ + kvh) * 128) * S_;

    auto load_q = [&](uint32_t dst, const unsigned short* src) {
#pragma unroll
        for (int it = 0; it < 8; it++) {
            int u = tid + it * 256;          // 128 rows x 256B
            int row = u >> 4;
            int cb = (u & 15) << 4;
            cp_async16(sb + dst + row * 272 + cb,
                       (const char*)src + (size_t)row * E_ * 2 + cb);
        }
    };
    auto load_k64 = [&](uint32_t dst, const unsigned short* src) {
#pragma unroll
        for (int it = 0; it < 4; it++) {
            int u = tid + it * 256;          // 64 rows x 256B
            int row = u >> 4;
            int cb = (u & 15) << 4;
            cp_async16(sb + dst + row * 272 + cb,
                       (const char*)src + (size_t)row * KVN_ * 2 + cb);
        }
    };
    auto load_v64 = [&](uint32_t dst, const unsigned short* src) {
#pragma unroll
        for (int it = 0; it < 4; it++) {
            int u = tid + it * 256;          // 128 rows x 128B
            int row = u >> 3;
            int cb = (u & 7) << 4;
            cp_async16(sb + dst + row * 144 + cb,
                       (const char*)src + (size_t)row * S_ * 2 + cb);
        }
    };
    auto issue_stage = [&](int stg, int kv0) {
        const uint32_t base = F4_ST0 + stg * F4_STAGE;
        load_k64(base,         khp + (size_t)kv0 * KVN_);
        load_k64(base + 17408, klp + (size_t)kv0 * KVN_);
        load_v64(base + 34816, vhp + kv0);
        load_v64(base + 53248, vlp + kv0);
        cp_commit();
    };

    // initial: Q + stage 0
    load_q(F4_Q, qp);
    issue_stage(0, 0);
    cp_wait<0>();
    __syncthreads();

    float oacc[16][4];
#pragma unroll
    for (int nt = 0; nt < 16; nt++)
#pragma unroll
        for (int i = 0; i < 4; i++) oacc[nt][i] = 0.f;
    float m0 = -1e30f, m1 = -1e30f, l0 = 0.f, l1 = 0.f;

    const int arow = w * 16 + (lane & 15);
    const uint32_t aoff_base = arow * 272 + ((lane >> 4) << 4);
    const int brow = (((lane >> 4) & 1) << 3) + (lane & 7);
    const uint32_t bko = brow * 272 + (((lane >> 3) & 1) << 4);
    const uint32_t bvo = brow * 144 + (((lane >> 3) & 1) << 4);

    int buf = 0;
    for (int kt = 0; kt < S_ / 64; kt++) {
        if (kt + 1 < S_ / 64) issue_stage(buf ^ 1, (kt + 1) * 64);
        const uint32_t sk = sb + F4_ST0 + buf * F4_STAGE;

        float sacc[8][4];
#pragma unroll
        for (int nt = 0; nt < 8; nt++)
#pragma unroll
            for (int i = 0; i < 4; i++) sacc[nt][i] = 0.f;

        // ---- S = Q K^T (Q single fp16, K hi/lo fp16) ----
#pragma unroll
        for (int ks = 0; ks < 8; ks++) {
            uint32_t aq[4];
            ldmx4(aq[0], aq[1], aq[2], aq[3], sb + F4_Q + aoff_base + ks * 32);
#pragma unroll
            for (int np = 0; np < 4; np++) {
                const uint32_t bo = bko + np * 16 * 272 + ks * 32;
                uint32_t bh0, bh1, bh2, bh3, bl0, bl1, bl2, bl3;
                ldmx4(bh0, bh1, bh2, bh3, sk + bo);
                ldmx4(bl0, bl1, bl2, bl3, sk + 17408 + bo);
                float* s0 = sacc[np * 2];
                float* s1 = sacc[np * 2 + 1];
                mma_f16(s0[0], s0[1], s0[2], s0[3], aq[0], aq[1], aq[2], aq[3], bh0, bh1);
                mma_f16(s1[0], s1[1], s1[2], s1[3], aq[0], aq[1], aq[2], aq[3], bh2, bh3);
                mma_f16(s0[0], s0[1], s0[2], s0[3], aq[0], aq[1], aq[2], aq[3], bl0, bl1);
                mma_f16(s1[0], s1[1], s1[2], s1[3], aq[0], aq[1], aq[2], aq[3], bl2, bl3);
            }
        }

        // ---- online softmax (exp2 domain) ----
        float mx0 = -1e30f, mx1 = -1e30f;
#pragma unroll
        for (int nt = 0; nt < 8; nt++) {
            sacc[nt][0] *= scale2; sacc[nt][1] *= scale2;
            sacc[nt][2] *= scale2; sacc[nt][3] *= scale2;
            mx0 = fmaxf(mx0, fmaxf(sacc[nt][0], sacc[nt][1]));
            mx1 = fmaxf(mx1, fmaxf(sacc[nt][2], sacc[nt][3]));
        }
        mx0 = fmaxf(mx0, __shfl_xor_sync(0xffffffffu, mx0, 1));
        mx0 = fmaxf(mx0, __shfl_xor_sync(0xffffffffu, mx0, 2));
        mx1 = fmaxf(mx1, __shfl_xor_sync(0xffffffffu, mx1, 1));
        mx1 = fmaxf(mx1, __shfl_xor_sync(0xffffffffu, mx1, 2));
        const float mn0 = fmaxf(m0, mx0), mn1 = fmaxf(m1, mx1);
        const float c0 = ex2f(m0 - mn0), c1 = ex2f(m1 - mn1);
        m0 = mn0; m1 = mn1;
        float sum0 = 0.f, sum1 = 0.f;
#pragma unroll
        for (int nt = 0; nt < 8; nt++) {
            sacc[nt][0] = ex2f(sacc[nt][0] - mn0);
            sacc[nt][1] = ex2f(sacc[nt][1] - mn0);
            sacc[nt][2] = ex2f(sacc[nt][2] - mn1);
            sacc[nt][3] = ex2f(sacc[nt][3] - mn1);
            sum0 += sacc[nt][0] + sacc[nt][1];
            sum1 += sacc[nt][2] + sacc[nt][3];
        }
#pragma unroll
        for (int nt = 0; nt < 16; nt++) {
            oacc[nt][0] *= c0; oacc[nt][1] *= c0;
            oacc[nt][2] *= c1; oacc[nt][3] *= c1;
        }
        sum0 += __shfl_xor_sync(0xffffffffu, sum0, 1);
        sum0 += __shfl_xor_sync(0xffffffffu, sum0, 2);
        sum1 += __shfl_xor_sync(0xffffffffu, sum1, 1);
        sum1 += __shfl_xor_sync(0xffffffffu, sum1, 2);
        l0 = l0 * c0 + sum0;
        l1 = l1 * c1 + sum1;

        // ---- O += P V (fp16: P single, V hi/lo) ----
#pragma unroll
        for (int j = 0; j < 4; j++) {
            const float* p0 = sacc[2 * j];
            const float* p1 = sacc[2 * j + 1];
            uint32_t ap[4];
            ap[0] = packhf(p0[0], p0[1]);
            ap[1] = packhf(p0[2], p0[3]);
            ap[2] = packhf(p1[0], p1[1]);
            ap[3] = packhf(p1[2], p1[3]);
#pragma unroll
            for (int np = 0; np < 8; np++) {
                const uint32_t bo = bvo + np * 16 * 144 + j * 32;
                uint32_t bh0, bh1, bh2, bh3, bl0, bl1, bl2, bl3;
                ldmx4(bh0, bh1, bh2, bh3, sk + 34816 + bo);
                ldmx4(bl0, bl1, bl2, bl3, sk + 53248 + bo);
                float* o0 = oacc[np * 2];
                float* o1 = oacc[np * 2 + 1];
                mma_f16(o0[0], o0[1], o0[2], o0[3], ap[0], ap[1], ap[2], ap[3], bh0, bh1);
                mma_f16(o1[0], o1[1], o1[2], o1[3], ap[0], ap[1], ap[2], ap[3], bh2, bh3);
                mma_f16(o0[0], o0[1], o0[2], o0[3], ap[0], ap[1], ap[2], ap[3], bl0, bl1);
                mma_f16(o1[0], o1[1], o1[2], o1[3], ap[0], ap[1], ap[2], ap[3], bl2, bl3);
            }
        }

        if (kt + 1 < S_ / 64) cp_wait<0>();
        __syncthreads();
        buf ^= 1;
    }

    // ---- epilogue: write single fp16 ----
    const float i0 = 1.f / l0, i1 = 1.f / l1;
    const int r0g = q0 + w * 16 + (lane >> 2);
    const int col0 = h * 128 + ((lane & 3) << 1);
#pragma unroll
    for (int nt = 0; nt < 16; nt++) {
        const int col = col0 + nt * 8;
        const size_t idx0 = (size_t)(b * S_ + r0g) * E_ + col;
        const size_t idx1 = (size_t)(b * S_ + r0g + 8) * E_ + col;
        *(uint32_t*)&Ohf[idx0] = packhf(oacc[nt][0] * i0, oacc[nt][1] * i0);
        *(uint32_t*)&Ohf[idx1] = packhf(oacc[nt][2] * i1, oacc[nt][3] * i1);
    }
}

// ================================ launch =====================================
extern "C" void kernel_launch(void* const* d_in, const int* in_sizes, int n_in,
                              void* d_out, int out_size) {
    const float* x   = (const float*)d_in[0];
    const float* Wq  = (const float*)d_in[1];
    const float* bq  = (const float*)d_in[2];
    const float* Wkv = (const float*)d_in[3];
    const float* bkv = (const float*)d_in[4];
    const float* Wo  = (const float*)d_in[5];
    float* out = (float*)d_out;

    float *qb, *kvb;
    cudaGetSymbolAddress((void**)&qb,  g_qproj);
    cudaGetSymbolAddress((void**)&kvb, g_kvproj);
    unsigned short *xhf, *wqhi, *wqlo, *wkvhi, *wkvlo, *wohi, *wolo, *ahf;
    unsigned short *qhf, *khi, *klo, *vthi, *vtlo;
    cudaGetSymbolAddress((void**)&xhf,  g_xhf);
    cudaGetSymbolAddress((void**)&wqhi, g_wqhi);
    cudaGetSymbolAddress((void**)&wqlo, g_wqlo);
    cudaGetSymbolAddress((void**)&wkvhi, g_wkvhi);
    cudaGetSymbolAddress((void**)&wkvlo, g_wkvlo);
    cudaGetSymbolAddress((void**)&wohi, g_wohi);
    cudaGetSymbolAddress((void**)&wolo, g_wolo);
    cudaGetSymbolAddress((void**)&ahf,  g_ahf);
    cudaGetSymbolAddress((void**)&qhf,  g_qhf);
    cudaGetSymbolAddress((void**)&khi,  g_khi);
    cudaGetSymbolAddress((void**)&klo,  g_klo);
    cudaGetSymbolAddress((void**)&vthi, g_vthi);
    cudaGetSymbolAddress((void**)&vtlo, g_vtlo);

    // fp32 -> fp16 conversions: x single; Wq/Wkv/Wo hi/lo
    {
        int n4;
        n4 = M_ * E_ / 4;   to_fp16<<<(n4 + 255) / 256, 256>>>(x, xhf, n4);
        n4 = E_ * E_ / 4;   split_fp16<<<(n4 + 255) / 256, 256>>>(Wq,  wqhi, wqlo, n4);
        n4 = KVN_ * E_ / 4; split_fp16<<<(n4 + 255) / 256, 256>>>(Wkv, wkvhi, wkvlo, n4);
        n4 = E_ * E_ / 4;   split_fp16<<<(n4 + 255) / 256, 256>>>(Wo,  wohi, wolo, n4);
    }

    // Q / KV projections (fp16 2-term, fp32 out)
    gemm_hf_x2<<<dim3(E_ / 128, M_ / 128), 256>>>(
        xhf, wqhi, wqlo, bq, qb, M_, E_, E_);
    gemm_hf_x2<<<dim3(KVN_ / 128, M_ / 128), 256>>>(
        xhf, wkvhi, wkvlo, bkv, kvb, M_, KVN_, E_);

    // RoPE: Q -> single fp16; K -> fp16 hi/lo. V transpose+split (fp16 hi/lo)
    {
        int totq = M_ * H_ * 64;
        rope_q_f16<<<(totq + 255) / 256, 256>>>(qb, qhf);
        int totk = M_ * KVH_ * 64;
        rope_k_f16hl<<<(totk + 255) / 256, 256>>>(kvb, khi, klo);
        vtrans_split<<<dim3(S_ / 32, D_ / 32, B_ * KVH_), 256>>>(kvb, vthi, vtlo);
    }

    // flash attention (fp16x2 QK, fp16x2 PV; writes single fp16 A)
    {
        cudaFuncSetAttribute(flash_hmma,
                             cudaFuncAttributeMaxDynamicSharedMemorySize, F4_SMEM);
        flash_hmma<<<dim3(S_ / 128, B_ * H_), 256, F4_SMEM>>>(
            qhf, khi, klo, vthi, vtlo, ahf);
    }

    // O projection: out = A @ Wo^T, fp16 2-term
    gemm_hf_x2<<<dim3(E_ / 128, M_ / 128), 256>>>(
        ahf, wohi, wolo, nullptr, out, M_, E_, E_);
}

// round 15
// speedup vs baseline: 3.2680x; 1.7480x over previous
#include <cuda_runtime.h>
#include <cuda_bf16.h>
#include <cuda_fp16.h>
#include <math.h>
#include <stdint.h>

// Problem constants
#define B_   2
#define S_   2048
#define E_   2048
#define H_   16
#define KVH_ 4
#define D_   128
#define M_   (B_ * S_)        // 4096 rows
#define KVN_ (2 * KVH_ * D_)  // 1024

// ---------------- scratch (device globals; no allocs allowed) ----------------
__device__ float g_qproj[(size_t)M_ * E_];
__device__ float g_kvproj[(size_t)M_ * KVN_];

__device__ unsigned short g_xhf[(size_t)M_ * E_];    // x single fp16
__device__ unsigned short g_wqhf[(size_t)E_ * E_];   // weights single fp16
__device__ unsigned short g_wkvhf[(size_t)KVN_ * E_];
__device__ unsigned short g_wohf[(size_t)E_ * E_];
__device__ unsigned short g_ahf[(size_t)M_ * E_];    // attention out, single fp16
// flash operands (all single fp16)
__device__ unsigned short g_qhf[(size_t)M_ * E_];    // rope'd Q
__device__ unsigned short g_khf[(size_t)M_ * KVN_];  // rope'd K
__device__ unsigned short g_vthf[(size_t)B_ * KVH_ * D_ * S_];  // V^T

// ============================ PTX helpers ====================================
__device__ __forceinline__ uint32_t smem_u32(const void* p) {
    uint32_t a;
    asm("{ .reg .u64 t; cvta.to.shared.u64 t, %1; cvt.u32.u64 %0, t; }"
        : "=r"(a) : "l"(p));
    return a;
}
__device__ __forceinline__ void cp_async16(uint32_t dst, const void* src) {
    asm volatile("cp.async.cg.shared.global [%0], [%1], 16;"
                 :: "r"(dst), "l"(src) : "memory");
}
__device__ __forceinline__ void cp_commit() {
    asm volatile("cp.async.commit_group;" ::: "memory");
}
template <int N>
__device__ __forceinline__ void cp_wait() {
    asm volatile("cp.async.wait_group %0;" :: "n"(N) : "memory");
}
__device__ __forceinline__ void ldmx4(uint32_t& r0, uint32_t& r1, uint32_t& r2,
                                      uint32_t& r3, uint32_t addr) {
    asm volatile("ldmatrix.sync.aligned.m8n8.x4.shared.b16 {%0,%1,%2,%3}, [%4];"
                 : "=r"(r0), "=r"(r1), "=r"(r2), "=r"(r3) : "r"(addr));
}
__device__ __forceinline__ void mma_f16(float& d0, float& d1, float& d2, float& d3,
                                        uint32_t a0, uint32_t a1, uint32_t a2,
                                        uint32_t a3, uint32_t b0, uint32_t b1) {
    asm volatile(
        "mma.sync.aligned.m16n8k16.row.col.f32.f16.f16.f32 "
        "{%0,%1,%2,%3}, {%4,%5,%6,%7}, {%8,%9}, {%0,%1,%2,%3};"
        : "+f"(d0), "+f"(d1), "+f"(d2), "+f"(d3)
        : "r"(a0), "r"(a1), "r"(a2), "r"(a3), "r"(b0), "r"(b1));
}
__device__ __forceinline__ float ex2f(float x) {
    float y;
    asm("ex2.approx.ftz.f32 %0, %1;" : "=f"(y) : "f"(x));
    return y;
}
__device__ __forceinline__ uint32_t packhf(float a, float b) {
    __half2 t = __floats2half2_rn(a, b);
    return *(uint32_t*)&t;
}

// ====================== fp32 -> fp16 convert =================================
__global__ void __launch_bounds__(256) to_fp16(const float* __restrict__ in,
                                               unsigned short* __restrict__ outp,
                                               int n4) {
    int i = blockIdx.x * blockDim.x + threadIdx.x;
    if (i >= n4) return;
    float4 v = ((const float4*)in)[i];
    ushort4 h;
    h.x = __half_as_ushort(__float2half_rn(v.x));
    h.y = __half_as_ushort(__float2half_rn(v.y));
    h.z = __half_as_ushort(__float2half_rn(v.z));
    h.w = __half_as_ushort(__float2half_rn(v.w));
    ((ushort4*)outp)[i] = h;
}

// ==================== RoPE -> single fp16 (Q or K layout) ====================
__global__ void __launch_bounds__(256)
rope_f16(const float* __restrict__ t, unsigned short* __restrict__ outp,
         int nHeads, int rowStride) {
    int idx = blockIdx.x * blockDim.x + threadIdx.x;
    int total = M_ * nHeads * 64;
    if (idx >= total) return;
    int i = idx & 63;
    int h = (idx >> 6) % nHeads;
    int m = idx / (64 * nHeads);
    int s = m & (S_ - 1);
    float inv = powf(10000.0f, -(float)i * (1.0f / 64.0f));
    float fr = (float)s * inv;
    float sn, cs;
    sincosf(fr, &sn, &cs);
    const float* p = t + (size_t)m * rowStride + h * 128 + i;
    float v1 = p[0], v2 = p[64];
    size_t o = (size_t)m * rowStride + h * 128 + i;
    outp[o]      = __half_as_ushort(__float2half_rn(v1 * cs - v2 * sn));
    outp[o + 64] = __half_as_ushort(__float2half_rn(v2 * cs + v1 * sn));
}

// ============ V transpose -> single fp16: kvproj V-part -> VT[d, s] ==========
__global__ void __launch_bounds__(256) vtrans_f16(const float* __restrict__ kv,
                                                  unsigned short* __restrict__ vthf) {
    __shared__ float t[32][33];
    const int s0 = blockIdx.x * 32, d0 = blockIdx.y * 32;
    const int bk = blockIdx.z;
    const int b = bk >> 2, kvh = bk & 3;
    const int tx = threadIdx.x & 31, ty = threadIdx.x >> 5;
#pragma unroll
    for (int i = 0; i < 4; i++) {
        int s = s0 + ty + i * 8;
        t[ty + i * 8][tx] =
            kv[(size_t)(b * S_ + s) * KVN_ + KVH_ * D_ + kvh * 128 + d0 + tx];
    }
    __syncthreads();
#pragma unroll
    for (int i = 0; i < 4; i++) {
        int d = d0 + ty + i * 8;
        float v = t[tx][ty + i * 8];
        size_t o = ((size_t)bk * 128 + d) * S_ + s0 + tx;
        vthf[o] = __half_as_ushort(__float2half_rn(v));
    }
}

// ========= fp16 GEMM: C = A@W^T (+bias), both operands single fp16 ===========
#define GS_STRIDE 80
#define GS_BUF    (128 * GS_STRIDE)

__global__ void __launch_bounds__(256)
gemm_hf(const unsigned short* __restrict__ Ahf, const unsigned short* __restrict__ Bhf,
        const float* __restrict__ bias, float* __restrict__ C,
        int M, int N, int K) {
    __shared__ __align__(16) unsigned char smem[4 * GS_BUF];
    const uint32_t sb = smem_u32(smem);
    const int tid = threadIdx.x;
    const int wid = tid >> 5, lane = tid & 31;
    const int wm = wid & 3;
    const int wn = wid >> 2;
    const int m0 = blockIdx.y * 128, n0 = blockIdx.x * 128;

    const int NCH = K >> 5;

    float acc[2][8][4];
#pragma unroll
    for (int mt = 0; mt < 2; mt++)
#pragma unroll
        for (int nt = 0; nt < 8; nt++)
#pragma unroll
            for (int i = 0; i < 4; i++) acc[mt][nt][i] = 0.f;

    auto issue = [&](int c, int buf) {
        const int kk = c << 5;
#pragma unroll
        for (int h = 0; h < 2; h++) {
            const int u = tid + h * 256;
            const int row = u >> 2;
            const int kb = (u & 3) << 3;
            cp_async16(sb + buf * GS_BUF + row * GS_STRIDE + (kb << 1),
                       Ahf + (size_t)(m0 + row) * K + kk + kb);
            cp_async16(sb + 2 * GS_BUF + buf * GS_BUF + row * GS_STRIDE + (kb << 1),
                       Bhf + (size_t)(n0 + row) * K + kk + kb);
        }
        cp_commit();
    };

    issue(0, 0);
    int buf = 0;
    for (int c = 0; c < NCH; c++) {
        if (c + 1 < NCH) { issue(c + 1, buf ^ 1); cp_wait<1>(); }
        else             { cp_wait<0>(); }
        __syncthreads();

        const uint32_t abase = sb + buf * GS_BUF;
        const uint32_t bbase = sb + 2 * GS_BUF + buf * GS_BUF;
#pragma unroll
        for (int ks = 0; ks < 2; ks++) {
            const int kbyte = ks * 32;
            uint32_t a[2][4];
#pragma unroll
            for (int mt = 0; mt < 2; mt++) {
                const int row = wm * 32 + mt * 16 + (lane & 15);
                ldmx4(a[mt][0], a[mt][1], a[mt][2], a[mt][3],
                      abase + row * GS_STRIDE + kbyte + ((lane >> 4) << 4));
            }
            uint32_t b[8][2];
#pragma unroll
            for (int np = 0; np < 4; np++) {
                const int row = wn * 64 + np * 16 + (((lane >> 4) & 1) << 3) + (lane & 7);
                uint32_t r0, r1, r2, r3;
                ldmx4(r0, r1, r2, r3,
                      bbase + row * GS_STRIDE + kbyte + (((lane >> 3) & 1) << 4));
                b[np * 2][0] = r0; b[np * 2][1] = r1;
                b[np * 2 + 1][0] = r2; b[np * 2 + 1][1] = r3;
            }
#pragma unroll
            for (int mt = 0; mt < 2; mt++)
#pragma unroll
                for (int nt = 0; nt < 8; nt++)
                    mma_f16(acc[mt][nt][0], acc[mt][nt][1],
                            acc[mt][nt][2], acc[mt][nt][3],
                            a[mt][0], a[mt][1], a[mt][2], a[mt][3],
                            b[nt][0], b[nt][1]);
        }
        __syncthreads();
        buf ^= 1;
    }

    const int mrow = m0 + wm * 32 + (lane >> 2);
    const int ncol0 = n0 + wn * 64 + ((lane & 3) << 1);
#pragma unroll
    for (int mt = 0; mt < 2; mt++) {
#pragma unroll
        for (int nt = 0; nt < 8; nt++) {
            const int n = ncol0 + nt * 8;
            float b0 = bias ? bias[n] : 0.f;
            float b1 = bias ? bias[n + 1] : 0.f;
            float2 v0 = make_float2(acc[mt][nt][0] + b0, acc[mt][nt][1] + b1);
            float2 v1 = make_float2(acc[mt][nt][2] + b0, acc[mt][nt][3] + b1);
            *(float2*)&C[(size_t)(mrow + mt * 16) * N + n] = v0;
            *(float2*)&C[(size_t)(mrow + mt * 16 + 8) * N + n] = v1;
        }
    }
}

// ========= flash attention: single-fp16 QK + single-fp16 PV ==================
// CTA: 128 q rows, 8 warps. KV tile BN=64, double-buffered stages.
#define F5_Q     0
#define F5_ST0   34816
#define F5_K     0
#define F5_V     17408
#define F5_STAGE 35840            // K 64x272 | V 128x144
#define F5_SMEM  (F5_ST0 + 2 * F5_STAGE)   // 106496 B

__global__ void __launch_bounds__(256)
flash_hmma(const unsigned short* __restrict__ qhf,
           const unsigned short* __restrict__ khf,
           const unsigned short* __restrict__ vthf,
           unsigned short* __restrict__ Ohf) {
    extern __shared__ __align__(16) unsigned char fsm2[];
    const uint32_t sb = smem_u32(fsm2);
    const int tid = threadIdx.x;
    const int w = tid >> 5, lane = tid & 31;
    const int bh = blockIdx.y;
    const int b = bh >> 4, h = bh & 15;
    const int kvh = h >> 2;
    const int q0 = blockIdx.x * 128;
    const float scale2 = 0.127518795f;    // (1/sqrt(128)) * log2(e)

    const unsigned short* qp  = qhf + (size_t)(b * S_ + q0) * E_ + h * 128;
    const unsigned short* khp = khf + (size_t)b * S_ * KVN_ + kvh * 128;
    const unsigned short* vhp = vthf + ((size_t)(b * KVH_ + kvh) * 128) * S_;

    auto load_q = [&](uint32_t dst, const unsigned short* src) {
#pragma unroll
        for (int it = 0; it < 8; it++) {
            int u = tid + it * 256;          // 128 rows x 256B
            int row = u >> 4;
            int cb = (u & 15) << 4;
            cp_async16(sb + dst + row * 272 + cb,
                       (const char*)src + (size_t)row * E_ * 2 + cb);
        }
    };
    auto issue_stage = [&](int stg, int kv0) {
        const uint32_t base = F5_ST0 + stg * F5_STAGE;
#pragma unroll
        for (int it = 0; it < 4; it++) {
            int u = tid + it * 256;          // K: 64 rows x 256B
            int row = u >> 4;
            int cb = (u & 15) << 4;
            cp_async16(sb + base + F5_K + row * 272 + cb,
                       (const char*)(khp + (size_t)kv0 * KVN_) +
                           (size_t)row * KVN_ * 2 + cb);
        }
#pragma unroll
        for (int it = 0; it < 4; it++) {
            int u = tid + it * 256;          // V: 128 rows x 128B
            int row = u >> 3;
            int cb = (u & 7) << 4;
            cp_async16(sb + base + F5_V + row * 144 + cb,
                       (const char*)(vhp + kv0) + (size_t)row * S_ * 2 + cb);
        }
        cp_commit();
    };

    // initial: Q + stage 0
    load_q(F5_Q, qp);
    issue_stage(0, 0);
    cp_wait<0>();
    __syncthreads();

    float oacc[16][4];
#pragma unroll
    for (int nt = 0; nt < 16; nt++)
#pragma unroll
        for (int i = 0; i < 4; i++) oacc[nt][i] = 0.f;
    float m0 = -1e30f, m1 = -1e30f, l0 = 0.f, l1 = 0.f;

    const int arow = w * 16 + (lane & 15);
    const uint32_t aoff_base = arow * 272 + ((lane >> 4) << 4);
    const int brow = (((lane >> 4) & 1) << 3) + (lane & 7);
    const uint32_t bko = brow * 272 + (((lane >> 3) & 1) << 4);
    const uint32_t bvo = brow * 144 + (((lane >> 3) & 1) << 4);

    int buf = 0;
    for (int kt = 0; kt < S_ / 64; kt++) {
        if (kt + 1 < S_ / 64) issue_stage(buf ^ 1, (kt + 1) * 64);
        const uint32_t sk = sb + F5_ST0 + buf * F5_STAGE;

        float sacc[8][4];
#pragma unroll
        for (int nt = 0; nt < 8; nt++)
#pragma unroll
            for (int i = 0; i < 4; i++) sacc[nt][i] = 0.f;

        // ---- S = Q K^T (single fp16) ----
#pragma unroll
        for (int ks = 0; ks < 8; ks++) {
            uint32_t aq[4];
            ldmx4(aq[0], aq[1], aq[2], aq[3], sb + F5_Q + aoff_base + ks * 32);
#pragma unroll
            for (int np = 0; np < 4; np++) {
                const uint32_t bo = bko + np * 16 * 272 + ks * 32;
                uint32_t bh0, bh1, bh2, bh3;
                ldmx4(bh0, bh1, bh2, bh3, sk + F5_K + bo);
                float* s0 = sacc[np * 2];
                float* s1 = sacc[np * 2 + 1];
                mma_f16(s0[0], s0[1], s0[2], s0[3], aq[0], aq[1], aq[2], aq[3], bh0, bh1);
                mma_f16(s1[0], s1[1], s1[2], s1[3], aq[0], aq[1], aq[2], aq[3], bh2, bh3);
            }
        }

        // ---- online softmax (exp2 domain) ----
        float mx0 = -1e30f, mx1 = -1e30f;
#pragma unroll
        for (int nt = 0; nt < 8; nt++) {
            sacc[nt][0] *= scale2; sacc[nt][1] *= scale2;
            sacc[nt][2] *= scale2; sacc[nt][3] *= scale2;
            mx0 = fmaxf(mx0, fmaxf(sacc[nt][0], sacc[nt][1]));
            mx1 = fmaxf(mx1, fmaxf(sacc[nt][2], sacc[nt][3]));
        }
        mx0 = fmaxf(mx0, __shfl_xor_sync(0xffffffffu, mx0, 1));
        mx0 = fmaxf(mx0, __shfl_xor_sync(0xffffffffu, mx0, 2));
        mx1 = fmaxf(mx1, __shfl_xor_sync(0xffffffffu, mx1, 1));
        mx1 = fmaxf(mx1, __shfl_xor_sync(0xffffffffu, mx1, 2));
        const float mn0 = fmaxf(m0, mx0), mn1 = fmaxf(m1, mx1);
        const float c0 = ex2f(m0 - mn0), c1 = ex2f(m1 - mn1);
        m0 = mn0; m1 = mn1;
        float sum0 = 0.f, sum1 = 0.f;
#pragma unroll
        for (int nt = 0; nt < 8; nt++) {
            sacc[nt][0] = ex2f(sacc[nt][0] - mn0);
            sacc[nt][1] = ex2f(sacc[nt][1] - mn0);
            sacc[nt][2] = ex2f(sacc[nt][2] - mn1);
            sacc[nt][3] = ex2f(sacc[nt][3] - mn1);
            sum0 += sacc[nt][0] + sacc[nt][1];
            sum1 += sacc[nt][2] + sacc[nt][3];
        }
#pragma unroll
        for (int nt = 0; nt < 16; nt++) {
            oacc[nt][0] *= c0; oacc[nt][1] *= c0;
            oacc[nt][2] *= c1; oacc[nt][3] *= c1;
        }
        sum0 += __shfl_xor_sync(0xffffffffu, sum0, 1);
        sum0 += __shfl_xor_sync(0xffffffffu, sum0, 2);
        sum1 += __shfl_xor_sync(0xffffffffu, sum1, 1);
        sum1 += __shfl_xor_sync(0xffffffffu, sum1, 2);
        l0 = l0 * c0 + sum0;
        l1 = l1 * c1 + sum1;

        // ---- O += P V (single fp16) ----
#pragma unroll
        for (int j = 0; j < 4; j++) {
            const float* p0 = sacc[2 * j];
            const float* p1 = sacc[2 * j + 1];
            uint32_t ap[4];
            ap[0] = packhf(p0[0], p0[1]);
            ap[1] = packhf(p0[2], p0[3]);
            ap[2] = packhf(p1[0], p1[1]);
            ap[3] = packhf(p1[2], p1[3]);
#pragma unroll
            for (int np = 0; np < 8; np++) {
                const uint32_t bo = bvo + np * 16 * 144 + j * 32;
                uint32_t bh0, bh1, bh2, bh3;
                ldmx4(bh0, bh1, bh2, bh3, sk + F5_V + bo);
                float* o0 = oacc[np * 2];
                float* o1 = oacc[np * 2 + 1];
                mma_f16(o0[0], o0[1], o0[2], o0[3], ap[0], ap[1], ap[2], ap[3], bh0, bh1);
                mma_f16(o1[0], o1[1], o1[2], o1[3], ap[0], ap[1], ap[2], ap[3], bh2, bh3);
            }
        }

        if (kt + 1 < S_ / 64) cp_wait<0>();
        __syncthreads();
        buf ^= 1;
    }

    // ---- epilogue: write single fp16 ----
    const float i0 = 1.f / l0, i1 = 1.f / l1;
    const int r0g = q0 + w * 16 + (lane >> 2);
    const int col0 = h * 128 + ((lane & 3) << 1);
#pragma unroll
    for (int nt = 0; nt < 16; nt++) {
        const int col = col0 + nt * 8;
        const size_t idx0 = (size_t)(b * S_ + r0g) * E_ + col;
        const size_t idx1 = (size_t)(b * S_ + r0g + 8) * E_ + col;
        *(uint32_t*)&Ohf[idx0] = packhf(oacc[nt][0] * i0, oacc[nt][1] * i0);
        *(uint32_t*)&Ohf[idx1] = packhf(oacc[nt][2] * i1, oacc[nt][3] * i1);
    }
}

// ================================ launch =====================================
extern "C" void kernel_launch(void* const* d_in, const int* in_sizes, int n_in,
                              void* d_out, int out_size) {
    const float* x   = (const float*)d_in[0];
    const float* Wq  = (const float*)d_in[1];
    const float* bq  = (const float*)d_in[2];
    const float* Wkv = (const float*)d_in[3];
    const float* bkv = (const float*)d_in[4];
    const float* Wo  = (const float*)d_in[5];
    float* out = (float*)d_out;

    float *qb, *kvb;
    cudaGetSymbolAddress((void**)&qb,  g_qproj);
    cudaGetSymbolAddress((void**)&kvb, g_kvproj);
    unsigned short *xhf, *wqhf, *wkvhf, *wohf, *ahf, *qhf, *khf, *vthf;
    cudaGetSymbolAddress((void**)&xhf,   g_xhf);
    cudaGetSymbolAddress((void**)&wqhf,  g_wqhf);
    cudaGetSymbolAddress((void**)&wkvhf, g_wkvhf);
    cudaGetSymbolAddress((void**)&wohf,  g_wohf);
    cudaGetSymbolAddress((void**)&ahf,   g_ahf);
    cudaGetSymbolAddress((void**)&qhf,   g_qhf);
    cudaGetSymbolAddress((void**)&khf,   g_khf);
    cudaGetSymbolAddress((void**)&vthf,  g_vthf);

    // fp32 -> fp16 converts
    {
        int n4;
        n4 = M_ * E_ / 4;   to_fp16<<<(n4 + 255) / 256, 256>>>(x,   xhf,  n4);
        n4 = E_ * E_ / 4;   to_fp16<<<(n4 + 255) / 256, 256>>>(Wq,  wqhf, n4);
        n4 = KVN_ * E_ / 4; to_fp16<<<(n4 + 255) / 256, 256>>>(Wkv, wkvhf, n4);
        n4 = E_ * E_ / 4;   to_fp16<<<(n4 + 255) / 256, 256>>>(Wo,  wohf, n4);
    }

    // Q / KV projections (single fp16, fp32 out)
    gemm_hf<<<dim3(E_ / 128, M_ / 128), 256>>>(
        xhf, wqhf, bq, qb, M_, E_, E_);
    gemm_hf<<<dim3(KVN_ / 128, M_ / 128), 256>>>(
        xhf, wkvhf, bkv, kvb, M_, KVN_, E_);

    // RoPE -> single fp16 (Q, K); V transpose -> single fp16
    {
        int totq = M_ * H_ * 64;
        rope_f16<<<(totq + 255) / 256, 256>>>(qb, qhf, H_, E_);
        int totk = M_ * KVH_ * 64;
        rope_f16<<<(totk + 255) / 256, 256>>>(kvb, khf, KVH_, KVN_);
        vtrans_f16<<<dim3(S_ / 32, D_ / 32, B_ * KVH_), 256>>>(kvb, vthf);
    }

    // flash attention (all single fp16; writes single fp16 A)
    {
        cudaFuncSetAttribute(flash_hmma,
                             cudaFuncAttributeMaxDynamicSharedMemorySize, F5_SMEM);
        flash_hmma<<<dim3(S_ / 128, B_ * H_), 256, F5_SMEM>>>(
            qhf, khf, vthf, ahf);
    }

    // O projection: out = A @ Wo^T (single fp16)
    gemm_hf<<<dim3(E_ / 128, M_ / 128), 256>>>(
        ahf, wohf, nullptr, out, M_, E_, E_);
}

// round 16
// speedup vs baseline: 3.4491x; 1.0554x over previous
#include <cuda_runtime.h>
#include <cuda_bf16.h>
#include <cuda_fp16.h>
#include <math.h>
#include <stdint.h>

// Problem constants
#define B_   2
#define S_   2048
#define E_   2048
#define H_   16
#define KVH_ 4
#define D_   128
#define M_   (B_ * S_)        // 4096 rows
#define KVN_ (2 * KVH_ * D_)  // 1024

// ---------------- scratch (device globals; no allocs allowed) ----------------
__device__ unsigned short g_qprojh[(size_t)M_ * E_];   // proj outputs, fp16
__device__ unsigned short g_kvprojh[(size_t)M_ * KVN_];

__device__ unsigned short g_xhf[(size_t)M_ * E_];    // x single fp16
__device__ unsigned short g_wqhf[(size_t)E_ * E_];   // weights single fp16
__device__ unsigned short g_wkvhf[(size_t)KVN_ * E_];
__device__ unsigned short g_wohf[(size_t)E_ * E_];
__device__ unsigned short g_ahf[(size_t)M_ * E_];    // attention out, single fp16
// flash operands (all single fp16)
__device__ unsigned short g_qhf[(size_t)M_ * E_];    // rope'd Q
__device__ unsigned short g_khf[(size_t)M_ * KVN_];  // rope'd K
__device__ unsigned short g_vthf[(size_t)B_ * KVH_ * D_ * S_];  // V^T

// ============================ PTX helpers ====================================
__device__ __forceinline__ uint32_t smem_u32(const void* p) {
    uint32_t a;
    asm("{ .reg .u64 t; cvta.to.shared.u64 t, %1; cvt.u32.u64 %0, t; }"
        : "=r"(a) : "l"(p));
    return a;
}
__device__ __forceinline__ void cp_async16(uint32_t dst, const void* src) {
    asm volatile("cp.async.cg.shared.global [%0], [%1], 16;"
                 :: "r"(dst), "l"(src) : "memory");
}
__device__ __forceinline__ void cp_commit() {
    asm volatile("cp.async.commit_group;" ::: "memory");
}
template <int N>
__device__ __forceinline__ void cp_wait() {
    asm volatile("cp.async.wait_group %0;" :: "n"(N) : "memory");
}
__device__ __forceinline__ void ldmx4(uint32_t& r0, uint32_t& r1, uint32_t& r2,
                                      uint32_t& r3, uint32_t addr) {
    asm volatile("ldmatrix.sync.aligned.m8n8.x4.shared.b16 {%0,%1,%2,%3}, [%4];"
                 : "=r"(r0), "=r"(r1), "=r"(r2), "=r"(r3) : "r"(addr));
}
__device__ __forceinline__ void mma_f16(float& d0, float& d1, float& d2, float& d3,
                                        uint32_t a0, uint32_t a1, uint32_t a2,
                                        uint32_t a3, uint32_t b0, uint32_t b1) {
    asm volatile(
        "mma.sync.aligned.m16n8k16.row.col.f32.f16.f16.f32 "
        "{%0,%1,%2,%3}, {%4,%5,%6,%7}, {%8,%9}, {%0,%1,%2,%3};"
        : "+f"(d0), "+f"(d1), "+f"(d2), "+f"(d3)
        : "r"(a0), "r"(a1), "r"(a2), "r"(a3), "r"(b0), "r"(b1));
}
__device__ __forceinline__ float ex2f(float x) {
    float y;
    asm("ex2.approx.ftz.f32 %0, %1;" : "=f"(y) : "f"(x));
    return y;
}
__device__ __forceinline__ uint32_t packhf(float a, float b) {
    __half2 t = __floats2half2_rn(a, b);
    return *(uint32_t*)&t;
}

// ============ merged fp32 -> fp16 convert (x, Wq, Wkv, Wo in one) ============
#define CN_X   (M_ * E_ / 4)
#define CN_WQ  (E_ * E_ / 4)
#define CN_WKV (KVN_ * E_ / 4)
#define CN_WO  (E_ * E_ / 4)
#define CN_TOT (CN_X + CN_WQ + CN_WKV + CN_WO)

__global__ void __launch_bounds__(256)
conv_all(const float* __restrict__ x, const float* __restrict__ Wq,
         const float* __restrict__ Wkv, const float* __restrict__ Wo,
         unsigned short* __restrict__ xh, unsigned short* __restrict__ wqh,
         unsigned short* __restrict__ wkvh, unsigned short* __restrict__ woh) {
    int i = blockIdx.x * blockDim.x + threadIdx.x;
    if (i >= CN_TOT) return;
    const float* src;
    unsigned short* dst;
    int j = i;
    if (j < CN_X) { src = x; dst = xh; }
    else if ((j -= CN_X) < CN_WQ) { src = Wq; dst = wqh; }
    else if ((j -= CN_WQ) < CN_WKV) { src = Wkv; dst = wkvh; }
    else { j -= CN_WKV; src = Wo; dst = woh; }
    float4 v = ((const float4*)src)[j];
    ushort4 h;
    h.x = __half_as_ushort(__float2half_rn(v.x));
    h.y = __half_as_ushort(__float2half_rn(v.y));
    h.z = __half_as_ushort(__float2half_rn(v.z));
    h.w = __half_as_ushort(__float2half_rn(v.w));
    ((ushort4*)dst)[j] = h;
}

// ==================== RoPE (fp16 in) -> single fp16 ==========================
__global__ void __launch_bounds__(256)
rope_f16(const unsigned short* __restrict__ t, unsigned short* __restrict__ outp,
         int nHeads, int rowStride) {
    int idx = blockIdx.x * blockDim.x + threadIdx.x;
    int total = M_ * nHeads * 64;
    if (idx >= total) return;
    int i = idx & 63;
    int h = (idx >> 6) % nHeads;
    int m = idx / (64 * nHeads);
    int s = m & (S_ - 1);
    float inv = powf(10000.0f, -(float)i * (1.0f / 64.0f));
    float fr = (float)s * inv;
    float sn, cs;
    sincosf(fr, &sn, &cs);
    const unsigned short* p = t + (size_t)m * rowStride + h * 128 + i;
    float v1 = __half2float(__ushort_as_half(p[0]));
    float v2 = __half2float(__ushort_as_half(p[64]));
    size_t o = (size_t)m * rowStride + h * 128 + i;
    outp[o]      = __half_as_ushort(__float2half_rn(v1 * cs - v2 * sn));
    outp[o + 64] = __half_as_ushort(__float2half_rn(v2 * cs + v1 * sn));
}

// ===== V transpose (fp16 in, exact passthrough): kvproj V -> VT[d, s] ========
__global__ void __launch_bounds__(256) vtrans_f16(const unsigned short* __restrict__ kv,
                                                  unsigned short* __restrict__ vthf) {
    __shared__ unsigned short t[32][33];
    const int s0 = blockIdx.x * 32, d0 = blockIdx.y * 32;
    const int bk = blockIdx.z;
    const int b = bk >> 2, kvh = bk & 3;
    const int tx = threadIdx.x & 31, ty = threadIdx.x >> 5;
#pragma unroll
    for (int i = 0; i < 4; i++) {
        int s = s0 + ty + i * 8;
        t[ty + i * 8][tx] =
            kv[(size_t)(b * S_ + s) * KVN_ + KVH_ * D_ + kvh * 128 + d0 + tx];
    }
    __syncthreads();
#pragma unroll
    for (int i = 0; i < 4; i++) {
        int d = d0 + ty + i * 8;
        size_t o = ((size_t)bk * 128 + d) * S_ + s0 + tx;
        vthf[o] = t[tx][ty + i * 8];
    }
}

// ========= fp16 GEMM mainloop (shared by fp32-out and fp16-out) ==============
#define GS_STRIDE 80
#define GS_BUF    (128 * GS_STRIDE)

// fp32-out variant (O projection)
__global__ void __launch_bounds__(256)
gemm_hf(const unsigned short* __restrict__ Ahf, const unsigned short* __restrict__ Bhf,
        const float* __restrict__ bias, float* __restrict__ C,
        int M, int N, int K) {
    __shared__ __align__(16) unsigned char smem[4 * GS_BUF];
    const uint32_t sb = smem_u32(smem);
    const int tid = threadIdx.x;
    const int wid = tid >> 5, lane = tid & 31;
    const int wm = wid & 3;
    const int wn = wid >> 2;
    const int m0 = blockIdx.y * 128, n0 = blockIdx.x * 128;
    const int NCH = K >> 5;

    float acc[2][8][4];
#pragma unroll
    for (int mt = 0; mt < 2; mt++)
#pragma unroll
        for (int nt = 0; nt < 8; nt++)
#pragma unroll
            for (int i = 0; i < 4; i++) acc[mt][nt][i] = 0.f;

    auto issue = [&](int c, int buf) {
        const int kk = c << 5;
#pragma unroll
        for (int h = 0; h < 2; h++) {
            const int u = tid + h * 256;
            const int row = u >> 2;
            const int kb = (u & 3) << 3;
            cp_async16(sb + buf * GS_BUF + row * GS_STRIDE + (kb << 1),
                       Ahf + (size_t)(m0 + row) * K + kk + kb);
            cp_async16(sb + 2 * GS_BUF + buf * GS_BUF + row * GS_STRIDE + (kb << 1),
                       Bhf + (size_t)(n0 + row) * K + kk + kb);
        }
        cp_commit();
    };

    issue(0, 0);
    int buf = 0;
    for (int c = 0; c < NCH; c++) {
        if (c + 1 < NCH) { issue(c + 1, buf ^ 1); cp_wait<1>(); }
        else             { cp_wait<0>(); }
        __syncthreads();
        const uint32_t abase = sb + buf * GS_BUF;
        const uint32_t bbase = sb + 2 * GS_BUF + buf * GS_BUF;
#pragma unroll
        for (int ks = 0; ks < 2; ks++) {
            const int kbyte = ks * 32;
            uint32_t a[2][4];
#pragma unroll
            for (int mt = 0; mt < 2; mt++) {
                const int row = wm * 32 + mt * 16 + (lane & 15);
                ldmx4(a[mt][0], a[mt][1], a[mt][2], a[mt][3],
                      abase + row * GS_STRIDE + kbyte + ((lane >> 4) << 4));
            }
            uint32_t b[8][2];
#pragma unroll
            for (int np = 0; np < 4; np++) {
                const int row = wn * 64 + np * 16 + (((lane >> 4) & 1) << 3) + (lane & 7);
                uint32_t r0, r1, r2, r3;
                ldmx4(r0, r1, r2, r3,
                      bbase + row * GS_STRIDE + kbyte + (((lane >> 3) & 1) << 4));
                b[np * 2][0] = r0; b[np * 2][1] = r1;
                b[np * 2 + 1][0] = r2; b[np * 2 + 1][1] = r3;
            }
#pragma unroll
            for (int mt = 0; mt < 2; mt++)
#pragma unroll
                for (int nt = 0; nt < 8; nt++)
                    mma_f16(acc[mt][nt][0], acc[mt][nt][1],
                            acc[mt][nt][2], acc[mt][nt][3],
                            a[mt][0], a[mt][1], a[mt][2], a[mt][3],
                            b[nt][0], b[nt][1]);
        }
        __syncthreads();
        buf ^= 1;
    }

    const int mrow = m0 + wm * 32 + (lane >> 2);
    const int ncol0 = n0 + wn * 64 + ((lane & 3) << 1);
#pragma unroll
    for (int mt = 0; mt < 2; mt++) {
#pragma unroll
        for (int nt = 0; nt < 8; nt++) {
            const int n = ncol0 + nt * 8;
            float b0 = bias ? bias[n] : 0.f;
            float b1 = bias ? bias[n + 1] : 0.f;
            float2 v0 = make_float2(acc[mt][nt][0] + b0, acc[mt][nt][1] + b1);
            float2 v1 = make_float2(acc[mt][nt][2] + b0, acc[mt][nt][3] + b1);
            *(float2*)&C[(size_t)(mrow + mt * 16) * N + n] = v0;
            *(float2*)&C[(size_t)(mrow + mt * 16 + 8) * N + n] = v1;
        }
    }
}

// fp16-out variant (+bias) for Q/KV projections
__global__ void __launch_bounds__(256)
gemm_hf_h(const unsigned short* __restrict__ Ahf, const unsigned short* __restrict__ Bhf,
          const float* __restrict__ bias, unsigned short* __restrict__ C,
          int M, int N, int K) {
    __shared__ __align__(16) unsigned char smem[4 * GS_BUF];
    const uint32_t sb = smem_u32(smem);
    const int tid = threadIdx.x;
    const int wid = tid >> 5, lane = tid & 31;
    const int wm = wid & 3;
    const int wn = wid >> 2;
    const int m0 = blockIdx.y * 128, n0 = blockIdx.x * 128;
    const int NCH = K >> 5;

    float acc[2][8][4];
#pragma unroll
    for (int mt = 0; mt < 2; mt++)
#pragma unroll
        for (int nt = 0; nt < 8; nt++)
#pragma unroll
            for (int i = 0; i < 4; i++) acc[mt][nt][i] = 0.f;

    auto issue = [&](int c, int buf) {
        const int kk = c << 5;
#pragma unroll
        for (int h = 0; h < 2; h++) {
            const int u = tid + h * 256;
            const int row = u >> 2;
            const int kb = (u & 3) << 3;
            cp_async16(sb + buf * GS_BUF + row * GS_STRIDE + (kb << 1),
                       Ahf + (size_t)(m0 + row) * K + kk + kb);
            cp_async16(sb + 2 * GS_BUF + buf * GS_BUF + row * GS_STRIDE + (kb << 1),
                       Bhf + (size_t)(n0 + row) * K + kk + kb);
        }
        cp_commit();
    };

    issue(0, 0);
    int buf = 0;
    for (int c = 0; c < NCH; c++) {
        if (c + 1 < NCH) { issue(c + 1, buf ^ 1); cp_wait<1>(); }
        else             { cp_wait<0>(); }
        __syncthreads();
        const uint32_t abase = sb + buf * GS_BUF;
        const uint32_t bbase = sb + 2 * GS_BUF + buf * GS_BUF;
#pragma unroll
        for (int ks = 0; ks < 2; ks++) {
            const int kbyte = ks * 32;
            uint32_t a[2][4];
#pragma unroll
            for (int mt = 0; mt < 2; mt++) {
                const int row = wm * 32 + mt * 16 + (lane & 15);
                ldmx4(a[mt][0], a[mt][1], a[mt][2], a[mt][3],
                      abase + row * GS_STRIDE + kbyte + ((lane >> 4) << 4));
            }
            uint32_t b[8][2];
#pragma unroll
            for (int np = 0; np < 4; np++) {
                const int row = wn * 64 + np * 16 + (((lane >> 4) & 1) << 3) + (lane & 7);
                uint32_t r0, r1, r2, r3;
                ldmx4(r0, r1, r2, r3,
                      bbase + row * GS_STRIDE + kbyte + (((lane >> 3) & 1) << 4));
                b[np * 2][0] = r0; b[np * 2][1] = r1;
                b[np * 2 + 1][0] = r2; b[np * 2 + 1][1] = r3;
            }
#pragma unroll
            for (int mt = 0; mt < 2; mt++)
#pragma unroll
                for (int nt = 0; nt < 8; nt++)
                    mma_f16(acc[mt][nt][0], acc[mt][nt][1],
                            acc[mt][nt][2], acc[mt][nt][3],
                            a[mt][0], a[mt][1], a[mt][2], a[mt][3],
                            b[nt][0], b[nt][1]);
        }
        __syncthreads();
        buf ^= 1;
    }

    const int mrow = m0 + wm * 32 + (lane >> 2);
    const int ncol0 = n0 + wn * 64 + ((lane & 3) << 1);
#pragma unroll
    for (int mt = 0; mt < 2; mt++) {
#pragma unroll
        for (int nt = 0; nt < 8; nt++) {
            const int n = ncol0 + nt * 8;
            const float b0 = bias[n];
            const float b1 = bias[n + 1];
            *(uint32_t*)&C[(size_t)(mrow + mt * 16) * N + n] =
                packhf(acc[mt][nt][0] + b0, acc[mt][nt][1] + b1);
            *(uint32_t*)&C[(size_t)(mrow + mt * 16 + 8) * N + n] =
                packhf(acc[mt][nt][2] + b0, acc[mt][nt][3] + b1);
        }
    }
}

// ========= flash attention: single-fp16 QK + single-fp16 PV ==================
// CTA: 128 q rows, 8 warps. KV tile BN=64, double-buffered stages.
#define F5_Q     0
#define F5_ST0   34816
#define F5_K     0
#define F5_V     17408
#define F5_STAGE 35840            // K 64x272 | V 128x144
#define F5_SMEM  (F5_ST0 + 2 * F5_STAGE)   // 106496 B

__global__ void __launch_bounds__(256, 2)
flash_hmma(const unsigned short* __restrict__ qhf,
           const unsigned short* __restrict__ khf,
           const unsigned short* __restrict__ vthf,
           unsigned short* __restrict__ Ohf) {
    extern __shared__ __align__(16) unsigned char fsm2[];
    const uint32_t sb = smem_u32(fsm2);
    const int tid = threadIdx.x;
    const int w = tid >> 5, lane = tid & 31;
    const int bh = blockIdx.y;
    const int b = bh >> 4, h = bh & 15;
    const int kvh = h >> 2;
    const int q0 = blockIdx.x * 128;
    const float scale2 = 0.127518795f;    // (1/sqrt(128)) * log2(e)

    const unsigned short* qp  = qhf + (size_t)(b * S_ + q0) * E_ + h * 128;
    const unsigned short* khp = khf + (size_t)b * S_ * KVN_ + kvh * 128;
    const unsigned short* vhp = vthf + ((size_t)(b * KVH_ + kvh) * 128) * S_;

    auto load_q = [&](uint32_t dst, const unsigned short* src) {
#pragma unroll
        for (int it = 0; it < 8; it++) {
            int u = tid + it * 256;          // 128 rows x 256B
            int row = u >> 4;
            int cb = (u & 15) << 4;
            cp_async16(sb + dst + row * 272 + cb,
                       (const char*)src + (size_t)row * E_ * 2 + cb);
        }
    };
    auto issue_stage = [&](int stg, int kv0) {
        const uint32_t base = F5_ST0 + stg * F5_STAGE;
#pragma unroll
        for (int it = 0; it < 4; it++) {
            int u = tid + it * 256;          // K: 64 rows x 256B
            int row = u >> 4;
            int cb = (u & 15) << 4;
            cp_async16(sb + base + F5_K + row * 272 + cb,
                       (const char*)(khp + (size_t)kv0 * KVN_) +
                           (size_t)row * KVN_ * 2 + cb);
        }
#pragma unroll
        for (int it = 0; it < 4; it++) {
            int u = tid + it * 256;          // V: 128 rows x 128B
            int row = u >> 3;
            int cb = (u & 7) << 4;
            cp_async16(sb + base + F5_V + row * 144 + cb,
                       (const char*)(vhp + kv0) + (size_t)row * S_ * 2 + cb);
        }
        cp_commit();
    };

    // initial: Q + stage 0
    load_q(F5_Q, qp);
    issue_stage(0, 0);
    cp_wait<0>();
    __syncthreads();

    float oacc[16][4];
#pragma unroll
    for (int nt = 0; nt < 16; nt++)
#pragma unroll
        for (int i = 0; i < 4; i++) oacc[nt][i] = 0.f;
    float m0 = -1e30f, m1 = -1e30f, l0 = 0.f, l1 = 0.f;

    const int arow = w * 16 + (lane & 15);
    const uint32_t aoff_base = arow * 272 + ((lane >> 4) << 4);
    const int brow = (((lane >> 4) & 1) << 3) + (lane & 7);
    const uint32_t bko = brow * 272 + (((lane >> 3) & 1) << 4);
    const uint32_t bvo = brow * 144 + (((lane >> 3) & 1) << 4);

    int buf = 0;
    for (int kt = 0; kt < S_ / 64; kt++) {
        if (kt + 1 < S_ / 64) issue_stage(buf ^ 1, (kt + 1) * 64);
        const uint32_t sk = sb + F5_ST0 + buf * F5_STAGE;

        float sacc[8][4];
#pragma unroll
        for (int nt = 0; nt < 8; nt++)
#pragma unroll
            for (int i = 0; i < 4; i++) sacc[nt][i] = 0.f;

        // ---- S = Q K^T (single fp16) ----
#pragma unroll
        for (int ks = 0; ks < 8; ks++) {
            uint32_t aq[4];
            ldmx4(aq[0], aq[1], aq[2], aq[3], sb + F5_Q + aoff_base + ks * 32);
#pragma unroll
            for (int np = 0; np < 4; np++) {
                const uint32_t bo = bko + np * 16 * 272 + ks * 32;
                uint32_t bh0, bh1, bh2, bh3;
                ldmx4(bh0, bh1, bh2, bh3, sk + F5_K + bo);
                float* s0 = sacc[np * 2];
                float* s1 = sacc[np * 2 + 1];
                mma_f16(s0[0], s0[1], s0[2], s0[3], aq[0], aq[1], aq[2], aq[3], bh0, bh1);
                mma_f16(s1[0], s1[1], s1[2], s1[3], aq[0], aq[1], aq[2], aq[3], bh2, bh3);
            }
        }

        // ---- online softmax (exp2 domain) ----
        float mx0 = -1e30f, mx1 = -1e30f;
#pragma unroll
        for (int nt = 0; nt < 8; nt++) {
            sacc[nt][0] *= scale2; sacc[nt][1] *= scale2;
            sacc[nt][2] *= scale2; sacc[nt][3] *= scale2;
            mx0 = fmaxf(mx0, fmaxf(sacc[nt][0], sacc[nt][1]));
            mx1 = fmaxf(mx1, fmaxf(sacc[nt][2], sacc[nt][3]));
        }
        mx0 = fmaxf(mx0, __shfl_xor_sync(0xffffffffu, mx0, 1));
        mx0 = fmaxf(mx0, __shfl_xor_sync(0xffffffffu, mx0, 2));
        mx1 = fmaxf(mx1, __shfl_xor_sync(0xffffffffu, mx1, 1));
        mx1 = fmaxf(mx1, __shfl_xor_sync(0xffffffffu, mx1, 2));
        const float mn0 = fmaxf(m0, mx0), mn1 = fmaxf(m1, mx1);
        const float c0 = ex2f(m0 - mn0), c1 = ex2f(m1 - mn1);
        m0 = mn0; m1 = mn1;
        float sum0 = 0.f, sum1 = 0.f;
#pragma unroll
        for (int nt = 0; nt < 8; nt++) {
            sacc[nt][0] = ex2f(sacc[nt][0] - mn0);
            sacc[nt][1] = ex2f(sacc[nt][1] - mn0);
            sacc[nt][2] = ex2f(sacc[nt][2] - mn1);
            sacc[nt][3] = ex2f(sacc[nt][3] - mn1);
            sum0 += sacc[nt][0] + sacc[nt][1];
            sum1 += sacc[nt][2] + sacc[nt][3];
        }
#pragma unroll
        for (int nt = 0; nt < 16; nt++) {
            oacc[nt][0] *= c0; oacc[nt][1] *= c0;
            oacc[nt][2] *= c1; oacc[nt][3] *= c1;
        }
        sum0 += __shfl_xor_sync(0xffffffffu, sum0, 1);
        sum0 += __shfl_xor_sync(0xffffffffu, sum0, 2);
        sum1 += __shfl_xor_sync(0xffffffffu, sum1, 1);
        sum1 += __shfl_xor_sync(0xffffffffu, sum1, 2);
        l0 = l0 * c0 + sum0;
        l1 = l1 * c1 + sum1;

        // ---- O += P V (single fp16) ----
#pragma unroll
        for (int j = 0; j < 4; j++) {
            const float* p0 = sacc[2 * j];
            const float* p1 = sacc[2 * j + 1];
            uint32_t ap[4];
            ap[0] = packhf(p0[0], p0[1]);
            ap[1] = packhf(p0[2], p0[3]);
            ap[2] = packhf(p1[0], p1[1]);
            ap[3] = packhf(p1[2], p1[3]);
#pragma unroll
            for (int np = 0; np < 8; np++) {
                const uint32_t bo = bvo + np * 16 * 144 + j * 32;
                uint32_t bh0, bh1, bh2, bh3;
                ldmx4(bh0, bh1, bh2, bh3, sk + F5_V + bo);
                float* o0 = oacc[np * 2];
                float* o1 = oacc[np * 2 + 1];
                mma_f16(o0[0], o0[1], o0[2], o0[3], ap[0], ap[1], ap[2], ap[3], bh0, bh1);
                mma_f16(o1[0], o1[1], o1[2], o1[3], ap[0], ap[1], ap[2], ap[3], bh2, bh3);
            }
        }

        if (kt + 1 < S_ / 64) cp_wait<0>();
        __syncthreads();
        buf ^= 1;
    }

    // ---- epilogue: write single fp16 ----
    const float i0 = 1.f / l0, i1 = 1.f / l1;
    const int r0g = q0 + w * 16 + (lane >> 2);
    const int col0 = h * 128 + ((lane & 3) << 1);
#pragma unroll
    for (int nt = 0; nt < 16; nt++) {
        const int col = col0 + nt * 8;
        const size_t idx0 = (size_t)(b * S_ + r0g) * E_ + col;
        const size_t idx1 = (size_t)(b * S_ + r0g + 8) * E_ + col;
        *(uint32_t*)&Ohf[idx0] = packhf(oacc[nt][0] * i0, oacc[nt][1] * i0);
        *(uint32_t*)&Ohf[idx1] = packhf(oacc[nt][2] * i1, oacc[nt][3] * i1);
    }
}

// ================================ launch =====================================
extern "C" void kernel_launch(void* const* d_in, const int* in_sizes, int n_in,
                              void* d_out, int out_size) {
    const float* x   = (const float*)d_in[0];
    const float* Wq  = (const float*)d_in[1];
    const float* bq  = (const float*)d_in[2];
    const float* Wkv = (const float*)d_in[3];
    const float* bkv = (const float*)d_in[4];
    const float* Wo  = (const float*)d_in[5];
    float* out = (float*)d_out;

    unsigned short *qph, *kvph;
    cudaGetSymbolAddress((void**)&qph,  g_qprojh);
    cudaGetSymbolAddress((void**)&kvph, g_kvprojh);
    unsigned short *xhf, *wqhf, *wkvhf, *wohf, *ahf, *qhf, *khf, *vthf;
    cudaGetSymbolAddress((void**)&xhf,   g_xhf);
    cudaGetSymbolAddress((void**)&wqhf,  g_wqhf);
    cudaGetSymbolAddress((void**)&wkvhf, g_wkvhf);
    cudaGetSymbolAddress((void**)&wohf,  g_wohf);
    cudaGetSymbolAddress((void**)&ahf,   g_ahf);
    cudaGetSymbolAddress((void**)&qhf,   g_qhf);
    cudaGetSymbolAddress((void**)&khf,   g_khf);
    cudaGetSymbolAddress((void**)&vthf,  g_vthf);

    // merged fp32 -> fp16 converts
    conv_all<<<(CN_TOT + 255) / 256, 256>>>(x, Wq, Wkv, Wo, xhf, wqhf, wkvhf, wohf);

    // Q / KV projections (single fp16, fp16 out + bias)
    gemm_hf_h<<<dim3(E_ / 128, M_ / 128), 256>>>(
        xhf, wqhf, bq, qph, M_, E_, E_);
    gemm_hf_h<<<dim3(KVN_ / 128, M_ / 128), 256>>>(
        xhf, wkvhf, bkv, kvph, M_, KVN_, E_);

    // RoPE -> single fp16 (Q, K); V transpose (fp16 passthrough)
    {
        int totq = M_ * H_ * 64;
        rope_f16<<<(totq + 255) / 256, 256>>>(qph, qhf, H_, E_);
        int totk = M_ * KVH_ * 64;
        rope_f16<<<(totk + 255) / 256, 256>>>(kvph, khf, KVH_, KVN_);
        vtrans_f16<<<dim3(S_ / 32, D_ / 32, B_ * KVH_), 256>>>(kvph, vthf);
    }

    // flash attention (all single fp16; writes single fp16 A)
    {
        cudaFuncSetAttribute(flash_hmma,
                             cudaFuncAttributeMaxDynamicSharedMemorySize, F5_SMEM);
        flash_hmma<<<dim3(S_ / 128, B_ * H_), 256, F5_SMEM>>>(
            qhf, khf, vthf, ahf);
    }

    // O projection: out = A @ Wo^T (single fp16, fp32 out)
    gemm_hf<<<dim3(E_ / 128, M_ / 128), 256>>>(
        ahf, wohf, nullptr, out, M_, E_, E_);
}